// round 6
// baseline (speedup 1.0000x reference)
#include <cuda_runtime.h>
#include <cuda_bf16.h>
#include <cuda_fp16.h>
#include <stdint.h>
#include <math.h>

#define DIM 128
#define HEADS 4
#define NEG_SLOPE 0.2f
#define MAX_N 50000
#define MAX_E 600000
#define SCAN_CHUNK 1024
#define MAX_NB ((MAX_N + SCAN_CHUNK - 1) / SCAN_CHUNK)

// ------------------- scratch (static device globals; no allocs) -------------------
__device__ __half2 g_hh[MAX_N * 64];     // transformed features, fp16 (message payload)
__device__ float g_skip[MAX_N * DIM];
__device__ float g_buf1[MAX_N * DIM];
__device__ float g_asrc[MAX_N * HEADS];
__device__ float g_adst[MAX_N * HEADS];
__device__ int   g_deg[MAX_N];           // zero-invariant: scan re-zeroes after use
__device__ int   g_off[MAX_N + 1];
__device__ int   g_cursor[MAX_N];
__device__ int   g_csr[MAX_E + MAX_N];
__device__ int   g_agg[MAX_NB];
__device__ int   g_flag[MAX_NB];         // zero-invariant: scatter re-zeroes
// combined transposed weights per layer: Bt[n][k]: n<128 -> W[k][n], else Wskip[k][n-128]
__device__ __nv_bfloat16 g_bhi[2 * 256 * 128];
__device__ __nv_bfloat16 g_blo[2 * 256 * 128];

// ------------------- weight prep (weights only) -------------------
__global__ void prep_weights(const float* __restrict__ W1, const float* __restrict__ Ws1,
                             const float* __restrict__ W2, const float* __restrict__ Ws2) {
    int idx = blockIdx.x * blockDim.x + threadIdx.x;
    if (idx >= 2 * 256 * 128) return;
    int layer = idx >> 15;
    int rem   = idx & 32767;
    int n     = rem >> 7;
    int k     = rem & 127;
    const float* W = layer ? (n < 128 ? W2 : Ws2) : (n < 128 ? W1 : Ws1);
    float v = W[k * 128 + (n & 127)];
    __nv_bfloat16 hi = __float2bfloat16(v);
    float lo = v - __bfloat162float(hi);
    g_bhi[idx] = hi;
    g_blo[idx] = __float2bfloat16(lo);
}

// ------------------- single-kernel scan with decoupled lookback -------------------
// deg counts come from hist (self-loop added here as +1). Re-zeroes g_deg after reading.
__global__ void scan_lookback(int N) {
    __shared__ int wsum[8];
    __shared__ int s_base;
    int tid = threadIdx.x;
    int lane = tid & 31, warp = tid >> 5;
    int b = blockIdx.x;
    int i0 = b * SCAN_CHUNK + tid * 4;

    int4 d = make_int4(0, 0, 0, 0);
    if (i0 + 3 < N) {
        d = *(const int4*)(g_deg + i0);
        *(int4*)(g_deg + i0) = make_int4(0, 0, 0, 0);
        d.x += 1; d.y += 1; d.z += 1; d.w += 1;   // self-loops
    } else {
        if (i0 + 0 < N) { d.x = g_deg[i0 + 0] + 1; g_deg[i0 + 0] = 0; }
        if (i0 + 1 < N) { d.y = g_deg[i0 + 1] + 1; g_deg[i0 + 1] = 0; }
        if (i0 + 2 < N) { d.z = g_deg[i0 + 2] + 1; g_deg[i0 + 2] = 0; }
        if (i0 + 3 < N) { d.w = g_deg[i0 + 3] + 1; g_deg[i0 + 3] = 0; }
    }
    int T = d.x + d.y + d.z + d.w;
    int v = T;
    #pragma unroll
    for (int o = 1; o < 32; o <<= 1) {
        int t = __shfl_up_sync(0xffffffffu, v, o);
        if (lane >= o) v += t;
    }
    if (lane == 31) wsum[warp] = v;
    __syncthreads();
    if (warp == 0) {
        int w = (lane < 8) ? wsum[lane] : 0;
        #pragma unroll
        for (int o = 1; o < 8; o <<= 1) {
            int t = __shfl_up_sync(0xffffffffu, w, o);
            if (lane >= o) w += t;
        }
        if (lane < 8) wsum[lane] = w;
        if (lane == 0) {
            g_agg[b] = wsum[7];
            __threadfence();
            atomicExch(&g_flag[b], 1);
        }
    }
    __syncthreads();
    int blk_total_scan = (warp ? wsum[warp - 1] : 0);

    if (warp == 0) {
        int base = 0;
        for (int i = lane; i < b; i += 32) {
            while (atomicAdd(&g_flag[i], 0) == 0) {}
            base += g_agg[i];
        }
        #pragma unroll
        for (int o = 16; o > 0; o >>= 1) base += __shfl_xor_sync(0xffffffffu, base, o);
        if (lane == 0) s_base = base;
    }
    __syncthreads();

    int excl = v - T + blk_total_scan + s_base;
    int p = excl;
    if (i0 + 0 < N) { g_cursor[i0 + 0] = p; g_off[i0 + 1] = p + d.x; p += d.x; }
    if (i0 + 1 < N) { g_cursor[i0 + 1] = p; g_off[i0 + 2] = p + d.y; p += d.y; }
    if (i0 + 2 < N) { g_cursor[i0 + 2] = p; g_off[i0 + 3] = p + d.z; p += d.z; }
    if (i0 + 3 < N) { g_cursor[i0 + 3] = p; g_off[i0 + 4] = p + d.w; }
    if (b == 0 && tid == 0) g_off[0] = 0;
}

__global__ void scatter_kernel(const int* __restrict__ src, const int* __restrict__ dst,
                               int E, int N) {
    int i = blockIdx.x * blockDim.x + threadIdx.x;
    if (i < MAX_NB) g_flag[i] = 0;   // reset lookback flags for next replay
    if (i < E) {
        int d = dst[i];
        int p = atomicAdd(&g_cursor[d], 1);
        g_csr[p] = src[i];
    } else if (i < E + N) {
        int n = i - E;
        int p = atomicAdd(&g_cursor[n], 1);
        g_csr[p] = n;
    }
}

// ------------------- HMMA helper -------------------
__device__ __forceinline__ void mma_bf16(float c[4], const uint32_t a[4], const uint32_t b[2]) {
    asm volatile(
        "mma.sync.aligned.m16n8k16.row.col.f32.bf16.bf16.f32 "
        "{%0,%1,%2,%3}, {%4,%5,%6,%7}, {%8,%9}, {%0,%1,%2,%3};"
        : "+f"(c[0]), "+f"(c[1]), "+f"(c[2]), "+f"(c[3])
        : "r"(a[0]), "r"(a[1]), "r"(a[2]), "r"(a[3]), "r"(b[0]), "r"(b[1]));
}

// ------------------- fused HMMA GEMM (h + skip) + att logits [+ hist side-blocks] -------
// Blocks [0, gemm_nb): GEMM tile M=64 x N=256. Blocks >= gemm_nb: degree histogram.
__global__ void __launch_bounds__(256, 2)
gat_mma_fused(const float* __restrict__ X,
              const uint32_t* __restrict__ Bhi, const uint32_t* __restrict__ Blo,
              const float* __restrict__ a_src, const float* __restrict__ a_dst,
              int nrows, int gemm_nb,
              const int* __restrict__ dst_h, int E_hist) {
    int tid = threadIdx.x;

    if ((int)blockIdx.x >= gemm_nb) {   // ---- histogram role ----
        int nbh = gridDim.x - gemm_nb;
        for (int i = (blockIdx.x - gemm_nb) * blockDim.x + tid; i < E_hist;
             i += nbh * blockDim.x)
            atomicAdd(&g_deg[dst_h[i]], 1);
        return;
    }

    extern __shared__ uint32_t dsm[];
    __shared__ float s_att[256];
    uint32_t* Ah = dsm;            // 64*68
    uint32_t* Al = dsm + 4352;
    uint32_t* Bh = dsm + 8704;     // 256*36
    uint32_t* Bl = dsm + 17920;

    int row0 = blockIdx.x * 64;
    if (tid < 128) { s_att[tid] = a_src[tid]; s_att[128 + tid] = a_dst[tid]; }

    #pragma unroll
    for (int it = 0; it < 16; it++) {
        int idx = tid + it * 256;
        int r = idx >> 6;
        int w = idx & 63;
        float x0 = 0.f, x1 = 0.f;
        int gr = row0 + r;
        if (gr < nrows) {
            float2 v = *(const float2*)(X + (size_t)gr * 128 + w * 2);
            x0 = v.x; x1 = v.y;
        }
        __nv_bfloat16 h0 = __float2bfloat16(x0);
        __nv_bfloat16 h1 = __float2bfloat16(x1);
        __nv_bfloat16 l0 = __float2bfloat16(x0 - __bfloat162float(h0));
        __nv_bfloat16 l1 = __float2bfloat16(x1 - __bfloat162float(h1));
        Ah[r * 68 + w] = ((uint32_t)__bfloat16_as_ushort(h1) << 16) | __bfloat16_as_ushort(h0);
        Al[r * 68 + w] = ((uint32_t)__bfloat16_as_ushort(l1) << 16) | __bfloat16_as_ushort(l0);
    }

    int lane = tid & 31, warp = tid >> 5;
    int mi = warp & 1, ni = warp >> 1;
    int g = lane >> 2, t = lane & 3;
    int mloc  = mi * 32;
    int nbase = ni * 64;

    float acc[2][8][4];
    #pragma unroll
    for (int a = 0; a < 2; a++)
        #pragma unroll
        for (int b = 0; b < 8; b++)
            #pragma unroll
            for (int c = 0; c < 4; c++) acc[a][b][c] = 0.f;

    for (int kc = 0; kc < 2; kc++) {
        if (kc) __syncthreads();
        #pragma unroll
        for (int it = 0; it < 32; it++) {
            int idx = tid + it * 256;
            int r = idx >> 5;
            int w = idx & 31;
            Bh[r * 36 + w] = Bhi[r * 64 + kc * 32 + w];
            Bl[r * 36 + w] = Blo[r * 64 + kc * 32 + w];
        }
        __syncthreads();

        #pragma unroll
        for (int p = 0; p < 3; p++) {
            const uint32_t* As = (p == 2) ? Al : Ah;
            const uint32_t* Bs = (p == 1) ? Bl : Bh;
            #pragma unroll
            for (int ksl = 0; ksl < 4; ksl++) {
                int aw = kc * 32 + ksl * 8 + t;
                uint32_t af[2][4];
                #pragma unroll
                for (int mt = 0; mt < 2; mt++) {
                    int rb = (mloc + mt * 16 + g) * 68;
                    af[mt][0] = As[rb + aw];
                    af[mt][1] = As[rb + 8 * 68 + aw];
                    af[mt][2] = As[rb + aw + 4];
                    af[mt][3] = As[rb + 8 * 68 + aw + 4];
                }
                int bw = ksl * 8 + t;
                #pragma unroll
                for (int nt = 0; nt < 8; nt++) {
                    uint32_t bf[2];
                    int rb = (nbase + nt * 8 + g) * 36;
                    bf[0] = Bs[rb + bw];
                    bf[1] = Bs[rb + bw + 4];
                    mma_bf16(acc[0][nt], af[0], bf);
                    mma_bf16(acc[1][nt], af[1], bf);
                }
            }
        }
    }

    int gr0 = row0 + mloc;
    if (ni < 2) {
        float ps[2][2][2], pd[2][2][2];
        #pragma unroll
        for (int a = 0; a < 2; a++)
            #pragma unroll
            for (int b = 0; b < 2; b++) {
                ps[a][b][0] = ps[a][b][1] = 0.f;
                pd[a][b][0] = pd[a][b][1] = 0.f;
            }
        #pragma unroll
        for (int mt = 0; mt < 2; mt++) {
            int r0 = gr0 + mt * 16 + g;
            int r1 = r0 + 8;
            #pragma unroll
            for (int nt = 0; nt < 8; nt++) {
                int col = nbase + nt * 8 + t * 2;
                int hh = nt >> 2;
                float s0 = s_att[col],       s1 = s_att[col + 1];
                float d0 = s_att[128 + col], d1 = s_att[128 + col + 1];
                ps[mt][0][hh] += acc[mt][nt][0] * s0 + acc[mt][nt][1] * s1;
                pd[mt][0][hh] += acc[mt][nt][0] * d0 + acc[mt][nt][1] * d1;
                ps[mt][1][hh] += acc[mt][nt][2] * s0 + acc[mt][nt][3] * s1;
                pd[mt][1][hh] += acc[mt][nt][2] * d0 + acc[mt][nt][3] * d1;
                if (r0 < nrows)
                    g_hh[(size_t)r0 * 64 + (col >> 1)] =
                        __floats2half2_rn(acc[mt][nt][0], acc[mt][nt][1]);
                if (r1 < nrows)
                    g_hh[(size_t)r1 * 64 + (col >> 1)] =
                        __floats2half2_rn(acc[mt][nt][2], acc[mt][nt][3]);
            }
        }
        #pragma unroll
        for (int mt = 0; mt < 2; mt++)
            #pragma unroll
            for (int rs = 0; rs < 2; rs++)
                #pragma unroll
                for (int hh = 0; hh < 2; hh++) {
                    float vs = ps[mt][rs][hh];
                    float vd = pd[mt][rs][hh];
                    vs += __shfl_xor_sync(0xffffffffu, vs, 1);
                    vs += __shfl_xor_sync(0xffffffffu, vs, 2);
                    vd += __shfl_xor_sync(0xffffffffu, vd, 1);
                    vd += __shfl_xor_sync(0xffffffffu, vd, 2);
                    if (t == 0) {
                        int r = gr0 + mt * 16 + g + rs * 8;
                        if (r < nrows) {
                            int head = ni * 2 + hh;
                            g_asrc[r * 4 + head] = vs;
                            g_adst[r * 4 + head] = vd;
                        }
                    }
                }
    } else {
        int cb = nbase - 128;
        #pragma unroll
        for (int mt = 0; mt < 2; mt++) {
            int r0 = gr0 + mt * 16 + g;
            int r1 = r0 + 8;
            #pragma unroll
            for (int nt = 0; nt < 8; nt++) {
                int col = cb + nt * 8 + t * 2;
                if (r0 < nrows)
                    *(float2*)(g_skip + (size_t)r0 * 128 + col) =
                        make_float2(acc[mt][nt][0], acc[mt][nt][1]);
                if (r1 < nrows)
                    *(float2*)(g_skip + (size_t)r1 * 128 + col) =
                        make_float2(acc[mt][nt][2], acc[mt][nt][3]);
            }
        }
    }
}

// ------------------- online-softmax aggregate (fp16 gather) + skip + bias + elu -------
// warp per node; 2 independent online-softmax slots for MLP, merged at the end.
__global__ void __launch_bounds__(256)
agg_kernel(const float* __restrict__ bias, float* __restrict__ out, int N) {
    int gw = (blockIdx.x * blockDim.x + threadIdx.x) >> 5;
    int lane = threadIdx.x & 31;
    if (gw >= N) return;
    int n = gw;
    int beg = g_off[n];
    int end = g_off[n + 1];
    int head = lane >> 3;

    float adh = g_adst[n * 4 + head];
    const uint2* H = (const uint2*)g_hh;   // row stride 32 uint2

    float m0 = -INFINITY, den0 = 0.f;
    float4 a0 = make_float4(0.f, 0.f, 0.f, 0.f);
    float m1 = -INFINITY, den1 = 0.f;
    float4 a1 = make_float4(0.f, 0.f, 0.f, 0.f);

    int j = beg;
    for (; j + 1 < end; j += 2) {
        int s0 = g_csr[j];
        int s1 = g_csr[j + 1];
        float e0 = g_asrc[s0 * 4 + head] + adh; e0 = (e0 > 0.f) ? e0 : NEG_SLOPE * e0;
        float e1 = g_asrc[s1 * 4 + head] + adh; e1 = (e1 > 0.f) ? e1 : NEG_SLOPE * e1;
        uint2 v0 = H[(size_t)s0 * 32 + lane];
        uint2 v1 = H[(size_t)s1 * 32 + lane];
        float2 f00 = __half22float2(*(__half2*)&v0.x);
        float2 f01 = __half22float2(*(__half2*)&v0.y);
        float2 f10 = __half22float2(*(__half2*)&v1.x);
        float2 f11 = __half22float2(*(__half2*)&v1.y);
        {
            float mn = fmaxf(m0, e0);
            float sc = __expf(m0 - mn), w = __expf(e0 - mn);
            den0 = den0 * sc + w;
            a0.x = a0.x * sc + w * f00.x;
            a0.y = a0.y * sc + w * f00.y;
            a0.z = a0.z * sc + w * f01.x;
            a0.w = a0.w * sc + w * f01.y;
            m0 = mn;
        }
        {
            float mn = fmaxf(m1, e1);
            float sc = __expf(m1 - mn), w = __expf(e1 - mn);
            den1 = den1 * sc + w;
            a1.x = a1.x * sc + w * f10.x;
            a1.y = a1.y * sc + w * f10.y;
            a1.z = a1.z * sc + w * f11.x;
            a1.w = a1.w * sc + w * f11.y;
            m1 = mn;
        }
    }
    if (j < end) {
        int s0 = g_csr[j];
        float e0 = g_asrc[s0 * 4 + head] + adh; e0 = (e0 > 0.f) ? e0 : NEG_SLOPE * e0;
        uint2 v0 = H[(size_t)s0 * 32 + lane];
        float2 f00 = __half22float2(*(__half2*)&v0.x);
        float2 f01 = __half22float2(*(__half2*)&v0.y);
        float mn = fmaxf(m0, e0);
        float sc = __expf(m0 - mn), w = __expf(e0 - mn);
        den0 = den0 * sc + w;
        a0.x = a0.x * sc + w * f00.x;
        a0.y = a0.y * sc + w * f00.y;
        a0.z = a0.z * sc + w * f01.x;
        a0.w = a0.w * sc + w * f01.y;
        m0 = mn;
    }

    // merge slots (slot0 always non-empty: every node has a self-loop)
    float M  = fmaxf(m0, m1);
    float s0 = __expf(m0 - M);
    float s1 = __expf(m1 - M);
    float denom = den0 * s0 + den1 * s1;
    float4 acc;
    acc.x = a0.x * s0 + a1.x * s1;
    acc.y = a0.y * s0 + a1.y * s1;
    acc.z = a0.z * s0 + a1.z * s1;
    acc.w = a0.w * s0 + a1.w * s1;

    float inv = 1.0f / (denom + 1e-16f);
    float4 b  = ((const float4*)bias)[lane];
    float4 sk = ((const float4*)g_skip)[(size_t)n * 32 + lane];
    float4 o;
    o.x = acc.x * inv + b.x + sk.x;
    o.y = acc.y * inv + b.y + sk.y;
    o.z = acc.z * inv + b.z + sk.z;
    o.w = acc.w * inv + b.w + sk.w;
    o.x = (o.x > 0.f) ? o.x : expm1f(o.x);
    o.y = (o.y > 0.f) ? o.y : expm1f(o.y);
    o.z = (o.z > 0.f) ? o.z : expm1f(o.z);
    o.w = (o.w > 0.f) ? o.w : expm1f(o.w);
    ((float4*)out)[(size_t)n * 32 + lane] = o;
}

// ------------------- launch -------------------
extern "C" void kernel_launch(void* const* d_in, const int* in_sizes, int n_in,
                              void* d_out, int out_size) {
    const float* x    = (const float*)d_in[0];
    const int*   ei   = (const int*)  d_in[1];
    const float* W1   = (const float*)d_in[2];
    const float* as1  = (const float*)d_in[3];
    const float* ad1  = (const float*)d_in[4];
    const float* b1   = (const float*)d_in[5];
    const float* Ws1  = (const float*)d_in[6];
    const float* W2   = (const float*)d_in[7];
    const float* as2  = (const float*)d_in[8];
    const float* ad2  = (const float*)d_in[9];
    const float* b2   = (const float*)d_in[10];
    const float* Ws2  = (const float*)d_in[11];

    int N = in_sizes[0] / DIM;
    int E = in_sizes[1] / 2;
    const int* src = ei;
    const int* dst = ei + E;

    float* buf1;  cudaGetSymbolAddress((void**)&buf1, g_buf1);
    __nv_bfloat16* bhi; cudaGetSymbolAddress((void**)&bhi, g_bhi);
    __nv_bfloat16* blo; cudaGetSymbolAddress((void**)&blo, g_blo);

    const size_t dyn = 27136 * 4;
    cudaFuncSetAttribute(gat_mma_fused, cudaFuncAttributeMaxDynamicSharedMemorySize, (int)dyn);

    int nb = (N + SCAN_CHUNK - 1) / SCAN_CHUNK;
    int gemm_blocks = (N + 63) / 64;
    int hist_blocks = 160;
    int warp_blocks = (N * 32 + 255) / 256;

    prep_weights<<<(2 * 256 * 128 + 255) / 256, 256>>>(W1, Ws1, W2, Ws2);
    // layer-1 GEMM + histogram fused in one launch
    gat_mma_fused<<<gemm_blocks + hist_blocks, 256, dyn>>>(
        x, (const uint32_t*)bhi, (const uint32_t*)blo, as1, ad1, N,
        gemm_blocks, dst, E);
    scan_lookback<<<nb, 256>>>(N);
    scatter_kernel<<<(E + N + 255) / 256, 256>>>(src, dst, E, N);
    agg_kernel<<<warp_blocks, 256>>>(b1, buf1, N);
    gat_mma_fused<<<gemm_blocks, 256, dyn>>>(
        buf1, (const uint32_t*)(bhi + 256 * 128), (const uint32_t*)(blo + 256 * 128),
        as2, ad2, N, gemm_blocks, nullptr, 0);
    agg_kernel<<<warp_blocks, 256>>>(b2, (float*)d_out, N);
}

// round 8
// speedup vs baseline: 1.0176x; 1.0176x over previous
#include <cuda_runtime.h>
#include <cuda_bf16.h>
#include <stdint.h>
#include <math.h>

#define DIM 128
#define HEADS 4
#define NEG_SLOPE 0.2f
#define MAX_N 50000
#define MAX_E 600000
#define SCAN_CHUNK 1024
#define MAX_NB ((MAX_N + SCAN_CHUNK - 1) / SCAN_CHUNK)
#define WPREP_BLKS 256   // 65536 weight elems / 256 thr

// ------------------- scratch (static device globals; no allocs) -------------------
__device__ float g_h[MAX_N * DIM];
__device__ float g_skip[MAX_N * DIM];
__device__ float g_buf1[MAX_N * DIM];
__device__ float g_asrc[MAX_N * HEADS];
__device__ float g_adst[MAX_N * HEADS];
__device__ int   g_deg[MAX_N];           // zero-invariant: scan re-zeroes after read
__device__ int   g_off[MAX_N + 1];
__device__ int   g_cursor[MAX_N];
__device__ int   g_csr[MAX_E + MAX_N];
__device__ int   g_agg[MAX_NB];
__device__ int   g_flag[MAX_NB];         // zero-invariant: scatter re-zeroes
// combined transposed weights per layer: Bt[n][k]: n<128 -> W[k][n], else Wskip[k][n-128]
__device__ __nv_bfloat16 g_bhi[2 * 256 * 128];
__device__ __nv_bfloat16 g_blo[2 * 256 * 128];

// ------------------- prep (weights) + degree histogram, role-split -------------------
__global__ void prep_hist(const float* __restrict__ W1, const float* __restrict__ Ws1,
                          const float* __restrict__ W2, const float* __restrict__ Ws2,
                          const int* __restrict__ dst, int E) {
    int tid = threadIdx.x;
    if ((int)blockIdx.x < WPREP_BLKS) {
        int idx = blockIdx.x * 256 + tid;                 // 0..65535
        int layer = idx >> 15;
        int rem   = idx & 32767;
        int n     = rem >> 7;
        int k     = rem & 127;
        const float* W = layer ? (n < 128 ? W2 : Ws2) : (n < 128 ? W1 : Ws1);
        float v = W[k * 128 + (n & 127)];
        __nv_bfloat16 hi = __float2bfloat16(v);
        float lo = v - __bfloat162float(hi);
        g_bhi[idx] = hi;
        g_blo[idx] = __float2bfloat16(lo);
    } else {
        int nbh = gridDim.x - WPREP_BLKS;
        for (int i = (blockIdx.x - WPREP_BLKS) * 256 + tid; i < E; i += nbh * 256)
            atomicAdd(&g_deg[dst[i]], 1);
    }
}

// ------------------- single-kernel scan with decoupled lookback (round-6 proven) -----
__global__ void scan_lookback(int N) {
    __shared__ int wsum[8];
    __shared__ int s_base;
    int tid = threadIdx.x;
    int lane = tid & 31, warp = tid >> 5;
    int b = blockIdx.x;
    int i0 = b * SCAN_CHUNK + tid * 4;

    int4 d = make_int4(0, 0, 0, 0);
    if (i0 + 3 < N) {
        d = *(const int4*)(g_deg + i0);
        *(int4*)(g_deg + i0) = make_int4(0, 0, 0, 0);
        d.x += 1; d.y += 1; d.z += 1; d.w += 1;   // self-loops
    } else {
        if (i0 + 0 < N) { d.x = g_deg[i0 + 0] + 1; g_deg[i0 + 0] = 0; }
        if (i0 + 1 < N) { d.y = g_deg[i0 + 1] + 1; g_deg[i0 + 1] = 0; }
        if (i0 + 2 < N) { d.z = g_deg[i0 + 2] + 1; g_deg[i0 + 2] = 0; }
        if (i0 + 3 < N) { d.w = g_deg[i0 + 3] + 1; g_deg[i0 + 3] = 0; }
    }
    int T = d.x + d.y + d.z + d.w;
    int v = T;
    #pragma unroll
    for (int o = 1; o < 32; o <<= 1) {
        int t = __shfl_up_sync(0xffffffffu, v, o);
        if (lane >= o) v += t;
    }
    if (lane == 31) wsum[warp] = v;
    __syncthreads();
    if (warp == 0) {
        int w = (lane < 8) ? wsum[lane] : 0;
        #pragma unroll
        for (int o = 1; o < 8; o <<= 1) {
            int t = __shfl_up_sync(0xffffffffu, w, o);
            if (lane >= o) w += t;
        }
        if (lane < 8) wsum[lane] = w;
        if (lane == 0) {
            g_agg[b] = wsum[7];
            __threadfence();
            atomicExch(&g_flag[b], 1);
        }
    }
    __syncthreads();
    int blk_scan = (warp ? wsum[warp - 1] : 0);

    if (warp == 0) {
        int base = 0;
        for (int i = lane; i < b; i += 32) {
            while (atomicAdd(&g_flag[i], 0) == 0) {}
            base += g_agg[i];
        }
        #pragma unroll
        for (int o = 16; o > 0; o >>= 1) base += __shfl_xor_sync(0xffffffffu, base, o);
        if (lane == 0) s_base = base;
    }
    __syncthreads();

    int excl = v - T + blk_scan + s_base;
    int p = excl;
    if (i0 + 0 < N) { g_cursor[i0 + 0] = p; g_off[i0 + 1] = p + d.x; p += d.x; }
    if (i0 + 1 < N) { g_cursor[i0 + 1] = p; g_off[i0 + 2] = p + d.y; p += d.y; }
    if (i0 + 2 < N) { g_cursor[i0 + 2] = p; g_off[i0 + 3] = p + d.z; p += d.z; }
    if (i0 + 3 < N) { g_cursor[i0 + 3] = p; g_off[i0 + 4] = p + d.w; }
    if (b == 0 && tid == 0) g_off[0] = 0;
}

__global__ void scatter_kernel(const int* __restrict__ src, const int* __restrict__ dst,
                               int E, int N) {
    int i = blockIdx.x * blockDim.x + threadIdx.x;
    if (i < MAX_NB) g_flag[i] = 0;   // reset lookback flags for next replay
    if (i < E) {
        int d = dst[i];
        int p = atomicAdd(&g_cursor[d], 1);
        g_csr[p] = src[i];
    } else if (i < E + N) {
        int n = i - E;
        int p = atomicAdd(&g_cursor[n], 1);
        g_csr[p] = n;
    }
}

// ------------------- HMMA helper -------------------
__device__ __forceinline__ void mma_bf16(float c[4], const uint32_t a[4], const uint32_t b[2]) {
    asm volatile(
        "mma.sync.aligned.m16n8k16.row.col.f32.bf16.bf16.f32 "
        "{%0,%1,%2,%3}, {%4,%5,%6,%7}, {%8,%9}, {%0,%1,%2,%3};"
        : "+f"(c[0]), "+f"(c[1]), "+f"(c[2]), "+f"(c[3])
        : "r"(a[0]), "r"(a[1]), "r"(a[2]), "r"(a[3]), "r"(b[0]), "r"(b[1]));
}

// ------------------- fused HMMA GEMM (h + skip) + attention logits (round-5 proven) --
__global__ void __launch_bounds__(256, 2)
gat_mma_fused(const float* __restrict__ X,
              const uint32_t* __restrict__ Bhi, const uint32_t* __restrict__ Blo,
              const float* __restrict__ a_src, const float* __restrict__ a_dst,
              int nrows) {
    extern __shared__ uint32_t dsm[];
    __shared__ float s_att[256];
    uint32_t* Ah = dsm;            // 64*68
    uint32_t* Al = dsm + 4352;
    uint32_t* Bh = dsm + 8704;     // 256*36
    uint32_t* Bl = dsm + 17920;

    int tid  = threadIdx.x;
    int row0 = blockIdx.x * 64;
    if (tid < 128) { s_att[tid] = a_src[tid]; s_att[128 + tid] = a_dst[tid]; }

    #pragma unroll
    for (int it = 0; it < 16; it++) {
        int idx = tid + it * 256;
        int r = idx >> 6;
        int w = idx & 63;
        float x0 = 0.f, x1 = 0.f;
        int gr = row0 + r;
        if (gr < nrows) {
            float2 v = *(const float2*)(X + (size_t)gr * 128 + w * 2);
            x0 = v.x; x1 = v.y;
        }
        __nv_bfloat16 h0 = __float2bfloat16(x0);
        __nv_bfloat16 h1 = __float2bfloat16(x1);
        __nv_bfloat16 l0 = __float2bfloat16(x0 - __bfloat162float(h0));
        __nv_bfloat16 l1 = __float2bfloat16(x1 - __bfloat162float(h1));
        Ah[r * 68 + w] = ((uint32_t)__bfloat16_as_ushort(h1) << 16) | __bfloat16_as_ushort(h0);
        Al[r * 68 + w] = ((uint32_t)__bfloat16_as_ushort(l1) << 16) | __bfloat16_as_ushort(l0);
    }

    int lane = tid & 31, warp = tid >> 5;
    int mi = warp & 1, ni = warp >> 1;
    int g = lane >> 2, t = lane & 3;
    int mloc  = mi * 32;
    int nbase = ni * 64;

    float acc[2][8][4];
    #pragma unroll
    for (int a = 0; a < 2; a++)
        #pragma unroll
        for (int b = 0; b < 8; b++)
            #pragma unroll
            for (int c = 0; c < 4; c++) acc[a][b][c] = 0.f;

    for (int kc = 0; kc < 2; kc++) {
        if (kc) __syncthreads();
        #pragma unroll
        for (int it = 0; it < 32; it++) {
            int idx = tid + it * 256;
            int r = idx >> 5;
            int w = idx & 31;
            Bh[r * 36 + w] = Bhi[r * 64 + kc * 32 + w];
            Bl[r * 36 + w] = Blo[r * 64 + kc * 32 + w];
        }
        __syncthreads();

        #pragma unroll
        for (int p = 0; p < 3; p++) {
            const uint32_t* As = (p == 2) ? Al : Ah;
            const uint32_t* Bs = (p == 1) ? Bl : Bh;
            #pragma unroll
            for (int ksl = 0; ksl < 4; ksl++) {
                int aw = kc * 32 + ksl * 8 + t;
                uint32_t af[2][4];
                #pragma unroll
                for (int mt = 0; mt < 2; mt++) {
                    int rb = (mloc + mt * 16 + g) * 68;
                    af[mt][0] = As[rb + aw];
                    af[mt][1] = As[rb + 8 * 68 + aw];
                    af[mt][2] = As[rb + aw + 4];
                    af[mt][3] = As[rb + 8 * 68 + aw + 4];
                }
                int bw = ksl * 8 + t;
                #pragma unroll
                for (int nt = 0; nt < 8; nt++) {
                    uint32_t bf[2];
                    int rb = (nbase + nt * 8 + g) * 36;
                    bf[0] = Bs[rb + bw];
                    bf[1] = Bs[rb + bw + 4];
                    mma_bf16(acc[0][nt], af[0], bf);
                    mma_bf16(acc[1][nt], af[1], bf);
                }
            }
        }
    }

    int gr0 = row0 + mloc;
    if (ni < 2) {
        float ps[2][2][2], pd[2][2][2];
        #pragma unroll
        for (int a = 0; a < 2; a++)
            #pragma unroll
            for (int b = 0; b < 2; b++) {
                ps[a][b][0] = ps[a][b][1] = 0.f;
                pd[a][b][0] = pd[a][b][1] = 0.f;
            }
        #pragma unroll
        for (int mt = 0; mt < 2; mt++) {
            int r0 = gr0 + mt * 16 + g;
            int r1 = r0 + 8;
            #pragma unroll
            for (int nt = 0; nt < 8; nt++) {
                int col = nbase + nt * 8 + t * 2;
                int hh = nt >> 2;
                float s0 = s_att[col],       s1 = s_att[col + 1];
                float d0 = s_att[128 + col], d1 = s_att[128 + col + 1];
                ps[mt][0][hh] += acc[mt][nt][0] * s0 + acc[mt][nt][1] * s1;
                pd[mt][0][hh] += acc[mt][nt][0] * d0 + acc[mt][nt][1] * d1;
                ps[mt][1][hh] += acc[mt][nt][2] * s0 + acc[mt][nt][3] * s1;
                pd[mt][1][hh] += acc[mt][nt][2] * d0 + acc[mt][nt][3] * d1;
                if (r0 < nrows)
                    *(float2*)(g_h + (size_t)r0 * 128 + col) =
                        make_float2(acc[mt][nt][0], acc[mt][nt][1]);
                if (r1 < nrows)
                    *(float2*)(g_h + (size_t)r1 * 128 + col) =
                        make_float2(acc[mt][nt][2], acc[mt][nt][3]);
            }
        }
        #pragma unroll
        for (int mt = 0; mt < 2; mt++)
            #pragma unroll
            for (int rs = 0; rs < 2; rs++)
                #pragma unroll
                for (int hh = 0; hh < 2; hh++) {
                    float vs = ps[mt][rs][hh];
                    float vd = pd[mt][rs][hh];
                    vs += __shfl_xor_sync(0xffffffffu, vs, 1);
                    vs += __shfl_xor_sync(0xffffffffu, vs, 2);
                    vd += __shfl_xor_sync(0xffffffffu, vd, 1);
                    vd += __shfl_xor_sync(0xffffffffu, vd, 2);
                    if (t == 0) {
                        int r = gr0 + mt * 16 + g + rs * 8;
                        if (r < nrows) {
                            int head = ni * 2 + hh;
                            g_asrc[r * 4 + head] = vs;
                            g_adst[r * 4 + head] = vd;
                        }
                    }
                }
    } else {
        int cb = nbase - 128;
        #pragma unroll
        for (int mt = 0; mt < 2; mt++) {
            int r0 = gr0 + mt * 16 + g;
            int r1 = r0 + 8;
            #pragma unroll
            for (int nt = 0; nt < 8; nt++) {
                int col = cb + nt * 8 + t * 2;
                if (r0 < nrows)
                    *(float2*)(g_skip + (size_t)r0 * 128 + col) =
                        make_float2(acc[mt][nt][0], acc[mt][nt][1]);
                if (r1 < nrows)
                    *(float2*)(g_skip + (size_t)r1 * 128 + col) =
                        make_float2(acc[mt][nt][2], acc[mt][nt][3]);
            }
        }
    }
}

// ------------------- online-softmax aggregate (rare rescale) + skip + bias + elu -----
__global__ void __launch_bounds__(256)
agg_kernel(const float* __restrict__ bias, float* __restrict__ out, int N) {
    int gw = (blockIdx.x * blockDim.x + threadIdx.x) >> 5;
    int lane = threadIdx.x & 31;
    if (gw >= N) return;
    int n = gw;
    int beg = g_off[n];
    int end = g_off[n + 1];
    int head = lane >> 3;

    float adh = g_adst[n * 4 + head];
    const float4* h4 = (const float4*)g_h;

    float m = -INFINITY;
    float denom = 0.0f;
    float4 acc = make_float4(0.f, 0.f, 0.f, 0.f);
    #pragma unroll 2
    for (int j = beg; j < end; j++) {
        int s = g_csr[j];                       // broadcast load
        float a = g_asrc[s * 4 + head];         // 4 distinct addrs / warp
        float e = a + adh; e = (e > 0.f) ? e : NEG_SLOPE * e;
        float4 v = h4[(size_t)s * 32 + lane];   // coalesced 512B/warp
        if (e > m) {                            // rare: ~ln(deg) hits per segment
            float sc = __expf(m - e);           // exp(-inf)=0 on first hit
            denom *= sc;
            acc.x *= sc; acc.y *= sc; acc.z *= sc; acc.w *= sc;
            m = e;
        }
        float w = __expf(e - m);
        denom += w;
        acc.x += w * v.x; acc.y += w * v.y; acc.z += w * v.z; acc.w += w * v.w;
    }
    float inv = 1.0f / (denom + 1e-16f);
    float4 b  = ((const float4*)bias)[lane];
    float4 sk = ((const float4*)g_skip)[(size_t)n * 32 + lane];
    float4 o;
    o.x = acc.x * inv + b.x + sk.x;
    o.y = acc.y * inv + b.y + sk.y;
    o.z = acc.z * inv + b.z + sk.z;
    o.w = acc.w * inv + b.w + sk.w;
    o.x = (o.x > 0.f) ? o.x : expm1f(o.x);
    o.y = (o.y > 0.f) ? o.y : expm1f(o.y);
    o.z = (o.z > 0.f) ? o.z : expm1f(o.z);
    o.w = (o.w > 0.f) ? o.w : expm1f(o.w);
    ((float4*)out)[(size_t)n * 32 + lane] = o;
}

// ------------------- launch -------------------
extern "C" void kernel_launch(void* const* d_in, const int* in_sizes, int n_in,
                              void* d_out, int out_size) {
    const float* x    = (const float*)d_in[0];
    const int*   ei   = (const int*)  d_in[1];
    const float* W1   = (const float*)d_in[2];
    const float* as1  = (const float*)d_in[3];
    const float* ad1  = (const float*)d_in[4];
    const float* b1   = (const float*)d_in[5];
    const float* Ws1  = (const float*)d_in[6];
    const float* W2   = (const float*)d_in[7];
    const float* as2  = (const float*)d_in[8];
    const float* ad2  = (const float*)d_in[9];
    const float* b2   = (const float*)d_in[10];
    const float* Ws2  = (const float*)d_in[11];

    int N = in_sizes[0] / DIM;
    int E = in_sizes[1] / 2;
    const int* src = ei;
    const int* dst = ei + E;

    float* buf1;  cudaGetSymbolAddress((void**)&buf1, g_buf1);
    __nv_bfloat16* bhi; cudaGetSymbolAddress((void**)&bhi, g_bhi);
    __nv_bfloat16* blo; cudaGetSymbolAddress((void**)&blo, g_blo);

    const size_t dyn = 27136 * 4;
    cudaFuncSetAttribute(gat_mma_fused, cudaFuncAttributeMaxDynamicSharedMemorySize, (int)dyn);

    int nb = (N + SCAN_CHUNK - 1) / SCAN_CHUNK;
    int gemm_blocks = (N + 63) / 64;
    int warp_blocks = (N * 32 + 255) / 256;

    prep_hist<<<WPREP_BLKS + 1024, 256>>>(W1, Ws1, W2, Ws2, dst, E);       // 0
    gat_mma_fused<<<gemm_blocks, 256, dyn>>>(                              // 1
        x, (const uint32_t*)bhi, (const uint32_t*)blo, as1, ad1, N);
    scan_lookback<<<nb, 256>>>(N);                                         // 2
    scatter_kernel<<<(E + N + 255) / 256, 256>>>(src, dst, E, N);          // 3
    agg_kernel<<<warp_blocks, 256>>>(b1, buf1, N);                         // 4
    gat_mma_fused<<<gemm_blocks, 256, dyn>>>(                              // 5
        buf1, (const uint32_t*)(bhi + 256 * 128), (const uint32_t*)(blo + 256 * 128),
        as2, ad2, N);
    agg_kernel<<<warp_blocks, 256>>>(b2, (float*)d_out, N);                // 6
}

// round 9
// speedup vs baseline: 1.0634x; 1.0451x over previous
#include <cuda_runtime.h>
#include <cuda_bf16.h>
#include <stdint.h>
#include <math.h>

#define DIM 128
#define HEADS 4
#define NEG_SLOPE 0.2f
#define MAX_N 50000
#define MAX_E 600000
#define SCAN_CHUNK 1024
#define MAX_NB ((MAX_N + SCAN_CHUNK - 1) / SCAN_CHUNK)
#define WPREP_BLKS 256   // 65536 weight elems / 256 thr

// ------------------- scratch (static device globals; no allocs) -------------------
__device__ float g_h[MAX_N * DIM];
__device__ float g_skip[MAX_N * DIM];
__device__ float g_buf1[MAX_N * DIM];
__device__ float g_asrc[MAX_N * HEADS];
__device__ float g_adst[MAX_N * HEADS];
__device__ int   g_deg[MAX_N];           // zero-invariant: scan re-zeroes after read
__device__ int   g_off[MAX_N + 1];
__device__ int   g_cursor[MAX_N];
__device__ int   g_csr[MAX_E + MAX_N];
__device__ int   g_agg[MAX_NB];
__device__ int   g_flag[MAX_NB];         // zero-invariant: scatter re-zeroes
// combined transposed weights per layer: Bt[n][k]: n<128 -> W[k][n], else Wskip[k][n-128]
__device__ __nv_bfloat16 g_bhi[2 * 256 * 128];
__device__ __nv_bfloat16 g_blo[2 * 256 * 128];

// ------------------- prep (weights) + degree histogram, role-split -------------------
__global__ void prep_hist(const float* __restrict__ W1, const float* __restrict__ Ws1,
                          const float* __restrict__ W2, const float* __restrict__ Ws2,
                          const int* __restrict__ dst, int E) {
    int tid = threadIdx.x;
    if ((int)blockIdx.x < WPREP_BLKS) {
        int idx = blockIdx.x * 256 + tid;                 // 0..65535
        int layer = idx >> 15;
        int rem   = idx & 32767;
        int n     = rem >> 7;
        int k     = rem & 127;
        const float* W = layer ? (n < 128 ? W2 : Ws2) : (n < 128 ? W1 : Ws1);
        float v = W[k * 128 + (n & 127)];
        __nv_bfloat16 hi = __float2bfloat16(v);
        float lo = v - __bfloat162float(hi);
        g_bhi[idx] = hi;
        g_blo[idx] = __float2bfloat16(lo);
    } else {
        int nbh = gridDim.x - WPREP_BLKS;
        for (int i = (blockIdx.x - WPREP_BLKS) * 256 + tid; i < E; i += nbh * 256)
            atomicAdd(&g_deg[dst[i]], 1);
    }
}

// ------------------- single-kernel scan with decoupled lookback -------------------
__global__ void scan_lookback(int N) {
    __shared__ int wsum[8];
    __shared__ int s_base;
    int tid = threadIdx.x;
    int lane = tid & 31, warp = tid >> 5;
    int b = blockIdx.x;
    int i0 = b * SCAN_CHUNK + tid * 4;

    int4 d = make_int4(0, 0, 0, 0);
    if (i0 + 3 < N) {
        d = *(const int4*)(g_deg + i0);
        *(int4*)(g_deg + i0) = make_int4(0, 0, 0, 0);
        d.x += 1; d.y += 1; d.z += 1; d.w += 1;   // self-loops
    } else {
        if (i0 + 0 < N) { d.x = g_deg[i0 + 0] + 1; g_deg[i0 + 0] = 0; }
        if (i0 + 1 < N) { d.y = g_deg[i0 + 1] + 1; g_deg[i0 + 1] = 0; }
        if (i0 + 2 < N) { d.z = g_deg[i0 + 2] + 1; g_deg[i0 + 2] = 0; }
        if (i0 + 3 < N) { d.w = g_deg[i0 + 3] + 1; g_deg[i0 + 3] = 0; }
    }
    int T = d.x + d.y + d.z + d.w;
    int v = T;
    #pragma unroll
    for (int o = 1; o < 32; o <<= 1) {
        int t = __shfl_up_sync(0xffffffffu, v, o);
        if (lane >= o) v += t;
    }
    if (lane == 31) wsum[warp] = v;
    __syncthreads();
    if (warp == 0) {
        int w = (lane < 8) ? wsum[lane] : 0;
        #pragma unroll
        for (int o = 1; o < 8; o <<= 1) {
            int t = __shfl_up_sync(0xffffffffu, w, o);
            if (lane >= o) w += t;
        }
        if (lane < 8) wsum[lane] = w;
        if (lane == 0) {
            g_agg[b] = wsum[7];
            __threadfence();
            atomicExch(&g_flag[b], 1);
        }
    }
    __syncthreads();
    int blk_scan = (warp ? wsum[warp - 1] : 0);

    if (warp == 0) {
        int base = 0;
        for (int i = lane; i < b; i += 32) {
            while (atomicAdd(&g_flag[i], 0) == 0) {}
            base += g_agg[i];
        }
        #pragma unroll
        for (int o = 16; o > 0; o >>= 1) base += __shfl_xor_sync(0xffffffffu, base, o);
        if (lane == 0) s_base = base;
    }
    __syncthreads();

    int excl = v - T + blk_scan + s_base;
    int p = excl;
    if (i0 + 0 < N) { g_cursor[i0 + 0] = p; g_off[i0 + 1] = p + d.x; p += d.x; }
    if (i0 + 1 < N) { g_cursor[i0 + 1] = p; g_off[i0 + 2] = p + d.y; p += d.y; }
    if (i0 + 2 < N) { g_cursor[i0 + 2] = p; g_off[i0 + 3] = p + d.z; p += d.z; }
    if (i0 + 3 < N) { g_cursor[i0 + 3] = p; g_off[i0 + 4] = p + d.w; }
    if (b == 0 && tid == 0) g_off[0] = 0;
}

__global__ void scatter_kernel(const int* __restrict__ src, const int* __restrict__ dst,
                               int E, int N) {
    int i = blockIdx.x * blockDim.x + threadIdx.x;
    if (i < MAX_NB) g_flag[i] = 0;   // reset lookback flags for next replay
    if (i < E) {
        int d = dst[i];
        int p = atomicAdd(&g_cursor[d], 1);
        g_csr[p] = src[i];
    } else if (i < E + N) {
        int n = i - E;
        int p = atomicAdd(&g_cursor[n], 1);
        g_csr[p] = n;
    }
}

// ------------------- HMMA helper -------------------
__device__ __forceinline__ void mma_bf16(float c[4], const uint32_t a[4], const uint32_t b[2]) {
    asm volatile(
        "mma.sync.aligned.m16n8k16.row.col.f32.bf16.bf16.f32 "
        "{%0,%1,%2,%3}, {%4,%5,%6,%7}, {%8,%9}, {%0,%1,%2,%3};"
        : "+f"(c[0]), "+f"(c[1]), "+f"(c[2]), "+f"(c[3])
        : "r"(a[0]), "r"(a[1]), "r"(a[2]), "r"(a[3]), "r"(b[0]), "r"(b[1]));
}

// ------------------- fused HMMA GEMM (h + skip) + attention logits -------------------
__global__ void __launch_bounds__(256, 2)
gat_mma_fused(const float* __restrict__ X,
              const uint32_t* __restrict__ Bhi, const uint32_t* __restrict__ Blo,
              const float* __restrict__ a_src, const float* __restrict__ a_dst,
              int nrows) {
    extern __shared__ uint32_t dsm[];
    __shared__ float s_att[256];
    uint32_t* Ah = dsm;            // 64*68
    uint32_t* Al = dsm + 4352;
    uint32_t* Bh = dsm + 8704;     // 256*36
    uint32_t* Bl = dsm + 17920;

    int tid  = threadIdx.x;
    int row0 = blockIdx.x * 64;
    if (tid < 128) { s_att[tid] = a_src[tid]; s_att[128 + tid] = a_dst[tid]; }

    #pragma unroll
    for (int it = 0; it < 16; it++) {
        int idx = tid + it * 256;
        int r = idx >> 6;
        int w = idx & 63;
        float x0 = 0.f, x1 = 0.f;
        int gr = row0 + r;
        if (gr < nrows) {
            float2 v = *(const float2*)(X + (size_t)gr * 128 + w * 2);
            x0 = v.x; x1 = v.y;
        }
        __nv_bfloat16 h0 = __float2bfloat16(x0);
        __nv_bfloat16 h1 = __float2bfloat16(x1);
        __nv_bfloat16 l0 = __float2bfloat16(x0 - __bfloat162float(h0));
        __nv_bfloat16 l1 = __float2bfloat16(x1 - __bfloat162float(h1));
        Ah[r * 68 + w] = ((uint32_t)__bfloat16_as_ushort(h1) << 16) | __bfloat16_as_ushort(h0);
        Al[r * 68 + w] = ((uint32_t)__bfloat16_as_ushort(l1) << 16) | __bfloat16_as_ushort(l0);
    }

    int lane = tid & 31, warp = tid >> 5;
    int mi = warp & 1, ni = warp >> 1;
    int g = lane >> 2, t = lane & 3;
    int mloc  = mi * 32;
    int nbase = ni * 64;

    float acc[2][8][4];
    #pragma unroll
    for (int a = 0; a < 2; a++)
        #pragma unroll
        for (int b = 0; b < 8; b++)
            #pragma unroll
            for (int c = 0; c < 4; c++) acc[a][b][c] = 0.f;

    for (int kc = 0; kc < 2; kc++) {
        if (kc) __syncthreads();
        #pragma unroll
        for (int it = 0; it < 32; it++) {
            int idx = tid + it * 256;
            int r = idx >> 5;
            int w = idx & 31;
            Bh[r * 36 + w] = Bhi[r * 64 + kc * 32 + w];
            Bl[r * 36 + w] = Blo[r * 64 + kc * 32 + w];
        }
        __syncthreads();

        #pragma unroll
        for (int p = 0; p < 3; p++) {
            const uint32_t* As = (p == 2) ? Al : Ah;
            const uint32_t* Bs = (p == 1) ? Bl : Bh;
            #pragma unroll
            for (int ksl = 0; ksl < 4; ksl++) {
                int aw = kc * 32 + ksl * 8 + t;
                uint32_t af[2][4];
                #pragma unroll
                for (int mt = 0; mt < 2; mt++) {
                    int rb = (mloc + mt * 16 + g) * 68;
                    af[mt][0] = As[rb + aw];
                    af[mt][1] = As[rb + 8 * 68 + aw];
                    af[mt][2] = As[rb + aw + 4];
                    af[mt][3] = As[rb + 8 * 68 + aw + 4];
                }
                int bw = ksl * 8 + t;
                #pragma unroll
                for (int nt = 0; nt < 8; nt++) {
                    uint32_t bf[2];
                    int rb = (nbase + nt * 8 + g) * 36;
                    bf[0] = Bs[rb + bw];
                    bf[1] = Bs[rb + bw + 4];
                    mma_bf16(acc[0][nt], af[0], bf);
                    mma_bf16(acc[1][nt], af[1], bf);
                }
            }
        }
    }

    int gr0 = row0 + mloc;
    if (ni < 2) {
        float ps[2][2][2], pd[2][2][2];
        #pragma unroll
        for (int a = 0; a < 2; a++)
            #pragma unroll
            for (int b = 0; b < 2; b++) {
                ps[a][b][0] = ps[a][b][1] = 0.f;
                pd[a][b][0] = pd[a][b][1] = 0.f;
            }
        #pragma unroll
        for (int mt = 0; mt < 2; mt++) {
            int r0 = gr0 + mt * 16 + g;
            int r1 = r0 + 8;
            #pragma unroll
            for (int nt = 0; nt < 8; nt++) {
                int col = nbase + nt * 8 + t * 2;
                int hh = nt >> 2;
                float s0 = s_att[col],       s1 = s_att[col + 1];
                float d0 = s_att[128 + col], d1 = s_att[128 + col + 1];
                ps[mt][0][hh] += acc[mt][nt][0] * s0 + acc[mt][nt][1] * s1;
                pd[mt][0][hh] += acc[mt][nt][0] * d0 + acc[mt][nt][1] * d1;
                ps[mt][1][hh] += acc[mt][nt][2] * s0 + acc[mt][nt][3] * s1;
                pd[mt][1][hh] += acc[mt][nt][2] * d0 + acc[mt][nt][3] * d1;
                if (r0 < nrows)
                    *(float2*)(g_h + (size_t)r0 * 128 + col) =
                        make_float2(acc[mt][nt][0], acc[mt][nt][1]);
                if (r1 < nrows)
                    *(float2*)(g_h + (size_t)r1 * 128 + col) =
                        make_float2(acc[mt][nt][2], acc[mt][nt][3]);
            }
        }
        #pragma unroll
        for (int mt = 0; mt < 2; mt++)
            #pragma unroll
            for (int rs = 0; rs < 2; rs++)
                #pragma unroll
                for (int hh = 0; hh < 2; hh++) {
                    float vs = ps[mt][rs][hh];
                    float vd = pd[mt][rs][hh];
                    vs += __shfl_xor_sync(0xffffffffu, vs, 1);
                    vs += __shfl_xor_sync(0xffffffffu, vs, 2);
                    vd += __shfl_xor_sync(0xffffffffu, vd, 1);
                    vd += __shfl_xor_sync(0xffffffffu, vd, 2);
                    if (t == 0) {
                        int r = gr0 + mt * 16 + g + rs * 8;
                        if (r < nrows) {
                            int head = ni * 2 + hh;
                            g_asrc[r * 4 + head] = vs;
                            g_adst[r * 4 + head] = vd;
                        }
                    }
                }
    } else {
        int cb = nbase - 128;
        #pragma unroll
        for (int mt = 0; mt < 2; mt++) {
            int r0 = gr0 + mt * 16 + g;
            int r1 = r0 + 8;
            #pragma unroll
            for (int nt = 0; nt < 8; nt++) {
                int col = cb + nt * 8 + t * 2;
                if (r0 < nrows)
                    *(float2*)(g_skip + (size_t)r0 * 128 + col) =
                        make_float2(acc[mt][nt][0], acc[mt][nt][1]);
                if (r1 < nrows)
                    *(float2*)(g_skip + (size_t)r1 * 128 + col) =
                        make_float2(acc[mt][nt][2], acc[mt][nt][3]);
            }
        }
    }
}

// ------------------- online-softmax aggregate, 4-edge batched loads -------------------
__global__ void __launch_bounds__(256)
agg_kernel(const float* __restrict__ bias, float* __restrict__ out, int N) {
    int gw = (blockIdx.x * blockDim.x + threadIdx.x) >> 5;
    int lane = threadIdx.x & 31;
    if (gw >= N) return;
    int n = gw;
    int beg = g_off[n];
    int end = g_off[n + 1];
    int head = lane >> 3;

    float adh = g_adst[n * 4 + head];
    const float4* h4 = (const float4*)g_h;

    float m = -INFINITY;
    float denom = 0.0f;
    float4 acc = make_float4(0.f, 0.f, 0.f, 0.f);

    int j = beg;
    for (; j + 4 <= end; j += 4) {
        // issue all loads up front (MLP ~ 5-6)
        int s0 = g_csr[j];
        int s1 = g_csr[j + 1];
        int s2 = g_csr[j + 2];
        int s3 = g_csr[j + 3];
        float a0 = g_asrc[s0 * 4 + head];
        float a1 = g_asrc[s1 * 4 + head];
        float a2 = g_asrc[s2 * 4 + head];
        float a3 = g_asrc[s3 * 4 + head];
        float4 v0 = h4[(size_t)s0 * 32 + lane];
        float4 v1 = h4[(size_t)s1 * 32 + lane];
        float4 v2 = h4[(size_t)s2 * 32 + lane];
        float4 v3 = h4[(size_t)s3 * 32 + lane];

        float e0 = a0 + adh; e0 = (e0 > 0.f) ? e0 : NEG_SLOPE * e0;
        float e1 = a1 + adh; e1 = (e1 > 0.f) ? e1 : NEG_SLOPE * e1;
        float e2 = a2 + adh; e2 = (e2 > 0.f) ? e2 : NEG_SLOPE * e2;
        float e3 = a3 + adh; e3 = (e3 > 0.f) ? e3 : NEG_SLOPE * e3;

        float mx = fmaxf(fmaxf(e0, e1), fmaxf(e2, e3));
        if (mx > m) {
            float sc = __expf(m - mx);   // exp(-inf)=0 on first batch
            denom *= sc;
            acc.x *= sc; acc.y *= sc; acc.z *= sc; acc.w *= sc;
            m = mx;
        }
        float w0 = __expf(e0 - m);
        float w1 = __expf(e1 - m);
        float w2 = __expf(e2 - m);
        float w3 = __expf(e3 - m);
        denom += (w0 + w1) + (w2 + w3);
        acc.x += w0 * v0.x + w1 * v1.x + w2 * v2.x + w3 * v3.x;
        acc.y += w0 * v0.y + w1 * v1.y + w2 * v2.y + w3 * v3.y;
        acc.z += w0 * v0.z + w1 * v1.z + w2 * v2.z + w3 * v3.z;
        acc.w += w0 * v0.w + w1 * v1.w + w2 * v2.w + w3 * v3.w;
    }
    for (; j < end; j++) {
        int s = g_csr[j];
        float a = g_asrc[s * 4 + head];
        float e = a + adh; e = (e > 0.f) ? e : NEG_SLOPE * e;
        float4 v = h4[(size_t)s * 32 + lane];
        if (e > m) {
            float sc = __expf(m - e);
            denom *= sc;
            acc.x *= sc; acc.y *= sc; acc.z *= sc; acc.w *= sc;
            m = e;
        }
        float w = __expf(e - m);
        denom += w;
        acc.x += w * v.x; acc.y += w * v.y; acc.z += w * v.z; acc.w += w * v.w;
    }

    float inv = 1.0f / (denom + 1e-16f);
    float4 b  = ((const float4*)bias)[lane];
    float4 sk = ((const float4*)g_skip)[(size_t)n * 32 + lane];
    float4 o;
    o.x = acc.x * inv + b.x + sk.x;
    o.y = acc.y * inv + b.y + sk.y;
    o.z = acc.z * inv + b.z + sk.z;
    o.w = acc.w * inv + b.w + sk.w;
    o.x = (o.x > 0.f) ? o.x : expm1f(o.x);
    o.y = (o.y > 0.f) ? o.y : expm1f(o.y);
    o.z = (o.z > 0.f) ? o.z : expm1f(o.z);
    o.w = (o.w > 0.f) ? o.w : expm1f(o.w);
    ((float4*)out)[(size_t)n * 32 + lane] = o;
}

// ------------------- launch -------------------
extern "C" void kernel_launch(void* const* d_in, const int* in_sizes, int n_in,
                              void* d_out, int out_size) {
    const float* x    = (const float*)d_in[0];
    const int*   ei   = (const int*)  d_in[1];
    const float* W1   = (const float*)d_in[2];
    const float* as1  = (const float*)d_in[3];
    const float* ad1  = (const float*)d_in[4];
    const float* b1   = (const float*)d_in[5];
    const float* Ws1  = (const float*)d_in[6];
    const float* W2   = (const float*)d_in[7];
    const float* as2  = (const float*)d_in[8];
    const float* ad2  = (const float*)d_in[9];
    const float* b2   = (const float*)d_in[10];
    const float* Ws2  = (const float*)d_in[11];

    int N = in_sizes[0] / DIM;
    int E = in_sizes[1] / 2;
    const int* src = ei;
    const int* dst = ei + E;

    float* buf1;  cudaGetSymbolAddress((void**)&buf1, g_buf1);
    __nv_bfloat16* bhi; cudaGetSymbolAddress((void**)&bhi, g_bhi);
    __nv_bfloat16* blo; cudaGetSymbolAddress((void**)&blo, g_blo);

    const size_t dyn = 27136 * 4;
    cudaFuncSetAttribute(gat_mma_fused, cudaFuncAttributeMaxDynamicSharedMemorySize, (int)dyn);

    int nb = (N + SCAN_CHUNK - 1) / SCAN_CHUNK;
    int gemm_blocks = (N + 63) / 64;
    int warp_blocks = (N * 32 + 255) / 256;

    // GEMM placed at launch index 3 (the profiled slot).
    prep_hist<<<WPREP_BLKS + 1024, 256>>>(W1, Ws1, W2, Ws2, dst, E);       // 0
    scan_lookback<<<nb, 256>>>(N);                                         // 1
    scatter_kernel<<<(E + N + 255) / 256, 256>>>(src, dst, E, N);          // 2
    gat_mma_fused<<<gemm_blocks, 256, dyn>>>(                              // 3 <- profiled
        x, (const uint32_t*)bhi, (const uint32_t*)blo, as1, ad1, N);
    agg_kernel<<<warp_blocks, 256>>>(b1, buf1, N);                         // 4
    gat_mma_fused<<<gemm_blocks, 256, dyn>>>(                              // 5
        buf1, (const uint32_t*)(bhi + 256 * 128), (const uint32_t*)(blo + 256 * 128),
        as2, ad2, N);
    agg_kernel<<<warp_blocks, 256>>>(b2, (float*)d_out, N);                // 6
}

// round 10
// speedup vs baseline: 1.1627x; 1.0934x over previous
#include <cuda_runtime.h>
#include <cuda_bf16.h>
#include <stdint.h>
#include <math.h>

#define DIM 128
#define HEADS 4
#define NEG_SLOPE 0.2f
#define MAX_N 50000
#define MAX_E 600000
#define SCAN_CHUNK 1024
#define MAX_NB ((MAX_N + SCAN_CHUNK - 1) / SCAN_CHUNK)
#define WPREP_BLKS 256   // 65536 weight elems / 256 thr

// ------------------- scratch (static device globals; no allocs) -------------------
__device__ float g_h[MAX_N * DIM];
__device__ float g_skip[MAX_N * DIM];
__device__ float g_buf1[MAX_N * DIM];
__device__ float g_asrc[MAX_N * HEADS];
__device__ float g_adst[MAX_N * HEADS];
__device__ int   g_deg[MAX_N];           // zero-invariant: scan re-zeroes after read
__device__ int   g_off[MAX_N + 1];
__device__ int   g_cursor[MAX_N];
__device__ int   g_csr[MAX_E + MAX_N];
__device__ int   g_agg[MAX_NB];
__device__ int   g_flag[MAX_NB];         // zero-invariant: scatter re-zeroes
// combined transposed weights per layer: Bt[n][k]: n<128 -> W[k][n], else Wskip[k][n-128]
__device__ __nv_bfloat16 g_bhi[2 * 256 * 128];
__device__ __nv_bfloat16 g_blo[2 * 256 * 128];

// ------------------- prep (weights) + degree histogram, role-split -------------------
__global__ void prep_hist(const float* __restrict__ W1, const float* __restrict__ Ws1,
                          const float* __restrict__ W2, const float* __restrict__ Ws2,
                          const int* __restrict__ dst, int E) {
    int tid = threadIdx.x;
    if ((int)blockIdx.x < WPREP_BLKS) {
        int idx = blockIdx.x * 256 + tid;                 // 0..65535
        int layer = idx >> 15;
        int rem   = idx & 32767;
        int n     = rem >> 7;
        int k     = rem & 127;
        const float* W = layer ? (n < 128 ? W2 : Ws2) : (n < 128 ? W1 : Ws1);
        float v = W[k * 128 + (n & 127)];
        __nv_bfloat16 hi = __float2bfloat16(v);
        float lo = v - __bfloat162float(hi);
        g_bhi[idx] = hi;
        g_blo[idx] = __float2bfloat16(lo);
    } else {
        int nbh = gridDim.x - WPREP_BLKS;
        for (int i = (blockIdx.x - WPREP_BLKS) * 256 + tid; i < E; i += nbh * 256)
            atomicAdd(&g_deg[dst[i]], 1);
    }
}

// ------------------- single-kernel scan with decoupled lookback -------------------
__global__ void scan_lookback(int N) {
    __shared__ int wsum[8];
    __shared__ int s_base;
    int tid = threadIdx.x;
    int lane = tid & 31, warp = tid >> 5;
    int b = blockIdx.x;
    int i0 = b * SCAN_CHUNK + tid * 4;

    int4 d = make_int4(0, 0, 0, 0);
    if (i0 + 3 < N) {
        d = *(const int4*)(g_deg + i0);
        *(int4*)(g_deg + i0) = make_int4(0, 0, 0, 0);
        d.x += 1; d.y += 1; d.z += 1; d.w += 1;   // self-loops
    } else {
        if (i0 + 0 < N) { d.x = g_deg[i0 + 0] + 1; g_deg[i0 + 0] = 0; }
        if (i0 + 1 < N) { d.y = g_deg[i0 + 1] + 1; g_deg[i0 + 1] = 0; }
        if (i0 + 2 < N) { d.z = g_deg[i0 + 2] + 1; g_deg[i0 + 2] = 0; }
        if (i0 + 3 < N) { d.w = g_deg[i0 + 3] + 1; g_deg[i0 + 3] = 0; }
    }
    int T = d.x + d.y + d.z + d.w;
    int v = T;
    #pragma unroll
    for (int o = 1; o < 32; o <<= 1) {
        int t = __shfl_up_sync(0xffffffffu, v, o);
        if (lane >= o) v += t;
    }
    if (lane == 31) wsum[warp] = v;
    __syncthreads();
    if (warp == 0) {
        int w = (lane < 8) ? wsum[lane] : 0;
        #pragma unroll
        for (int o = 1; o < 8; o <<= 1) {
            int t = __shfl_up_sync(0xffffffffu, w, o);
            if (lane >= o) w += t;
        }
        if (lane < 8) wsum[lane] = w;
        if (lane == 0) {
            g_agg[b] = wsum[7];
            __threadfence();
            atomicExch(&g_flag[b], 1);
        }
    }
    __syncthreads();
    int blk_scan = (warp ? wsum[warp - 1] : 0);

    if (warp == 0) {
        int base = 0;
        for (int i = lane; i < b; i += 32) {
            while (atomicAdd(&g_flag[i], 0) == 0) {}
            base += g_agg[i];
        }
        #pragma unroll
        for (int o = 16; o > 0; o >>= 1) base += __shfl_xor_sync(0xffffffffu, base, o);
        if (lane == 0) s_base = base;
    }
    __syncthreads();

    int excl = v - T + blk_scan + s_base;
    int p = excl;
    if (i0 + 0 < N) { g_cursor[i0 + 0] = p; g_off[i0 + 1] = p + d.x; p += d.x; }
    if (i0 + 1 < N) { g_cursor[i0 + 1] = p; g_off[i0 + 2] = p + d.y; p += d.y; }
    if (i0 + 2 < N) { g_cursor[i0 + 2] = p; g_off[i0 + 3] = p + d.z; p += d.z; }
    if (i0 + 3 < N) { g_cursor[i0 + 3] = p; g_off[i0 + 4] = p + d.w; }
    if (b == 0 && tid == 0) g_off[0] = 0;
}

__global__ void scatter_kernel(const int* __restrict__ src, const int* __restrict__ dst,
                               int E, int N) {
    int i = blockIdx.x * blockDim.x + threadIdx.x;
    if (i < MAX_NB) g_flag[i] = 0;   // reset lookback flags for next replay
    if (i < E) {
        int d = dst[i];
        int p = atomicAdd(&g_cursor[d], 1);
        g_csr[p] = src[i];
    } else if (i < E + N) {
        int n = i - E;
        int p = atomicAdd(&g_cursor[n], 1);
        g_csr[p] = n;
    }
}

// ------------------- MMA / ldmatrix helpers -------------------
__device__ __forceinline__ void mma_bf16(float c[4], const uint32_t a[4],
                                         uint32_t b0, uint32_t b1) {
    asm volatile(
        "mma.sync.aligned.m16n8k16.row.col.f32.bf16.bf16.f32 "
        "{%0,%1,%2,%3}, {%4,%5,%6,%7}, {%8,%9}, {%0,%1,%2,%3};"
        : "+f"(c[0]), "+f"(c[1]), "+f"(c[2]), "+f"(c[3])
        : "r"(a[0]), "r"(a[1]), "r"(a[2]), "r"(a[3]), "r"(b0), "r"(b1));
}
__device__ __forceinline__ void ldsm_x4(uint32_t d[4], uint32_t addr) {
    asm volatile("ldmatrix.sync.aligned.m8n8.x4.shared.b16 {%0,%1,%2,%3}, [%4];"
                 : "=r"(d[0]), "=r"(d[1]), "=r"(d[2]), "=r"(d[3]) : "r"(addr));
}
__device__ __forceinline__ uint32_t s2u(const void* p) {
    return (uint32_t)__cvta_generic_to_shared(p);
}

// ------------------- fused HMMA GEMM (h + skip) + attention logits -------------------
// Mainloop fragments via ldmatrix.x4; product order per k-step: Ah*Bh, Al*Bh, Ah*Bl.
__global__ void __launch_bounds__(256, 2)
gat_mma_fused(const float* __restrict__ X,
              const uint32_t* __restrict__ Bhi, const uint32_t* __restrict__ Blo,
              const float* __restrict__ a_src, const float* __restrict__ a_dst,
              int nrows) {
    extern __shared__ uint32_t dsm[];
    __shared__ float s_att[256];
    uint32_t* Ah = dsm;            // 64*68
    uint32_t* Al = dsm + 4352;
    uint32_t* Bh = dsm + 8704;     // 256*36
    uint32_t* Bl = dsm + 17920;

    int tid  = threadIdx.x;
    int row0 = blockIdx.x * 64;
    if (tid < 128) { s_att[tid] = a_src[tid]; s_att[128 + tid] = a_dst[tid]; }

    #pragma unroll
    for (int it = 0; it < 16; it++) {
        int idx = tid + it * 256;
        int r = idx >> 6;
        int w = idx & 63;
        float x0 = 0.f, x1 = 0.f;
        int gr = row0 + r;
        if (gr < nrows) {
            float2 v = *(const float2*)(X + (size_t)gr * 128 + w * 2);
            x0 = v.x; x1 = v.y;
        }
        __nv_bfloat16 h0 = __float2bfloat16(x0);
        __nv_bfloat16 h1 = __float2bfloat16(x1);
        __nv_bfloat16 l0 = __float2bfloat16(x0 - __bfloat162float(h0));
        __nv_bfloat16 l1 = __float2bfloat16(x1 - __bfloat162float(h1));
        Ah[r * 68 + w] = ((uint32_t)__bfloat16_as_ushort(h1) << 16) | __bfloat16_as_ushort(h0);
        Al[r * 68 + w] = ((uint32_t)__bfloat16_as_ushort(l1) << 16) | __bfloat16_as_ushort(l0);
    }

    int lane = tid & 31, warp = tid >> 5;
    int mi = warp & 1, ni = warp >> 1;
    int g = lane >> 2, t = lane & 3;
    int mloc  = mi * 32;
    int nbase = ni * 64;

    // per-lane ldmatrix address offsets (bytes)
    // A: lanes 0-7 m0(rows 0-7, klo), 8-15 m1(rows 8-15, klo), 16-23 m2(rows 0-7, khi), 24-31 m3
    uint32_t a_off = (uint32_t)(((mloc + (lane & 15)) * 68 + ((lane >> 4) << 2)) * 4);
    uint32_t ah_base = s2u(Ah) + a_off;
    uint32_t al_base = s2u(Al) + a_off;
    // B: m0/m1 = n rows 0-7 (klo/khi), m2/m3 = n rows 8-15 (klo/khi)
    uint32_t b_off = (uint32_t)((((nbase + ((lane >> 4) << 3) + (lane & 7)) * 36)
                                 + (((lane >> 3) & 1) << 2)) * 4);
    uint32_t bh_base = s2u(Bh) + b_off;
    uint32_t bl_base = s2u(Bl) + b_off;

    float acc[2][8][4];
    #pragma unroll
    for (int a = 0; a < 2; a++)
        #pragma unroll
        for (int b = 0; b < 8; b++)
            #pragma unroll
            for (int c = 0; c < 4; c++) acc[a][b][c] = 0.f;

    for (int kc = 0; kc < 2; kc++) {
        if (kc) __syncthreads();
        #pragma unroll
        for (int it = 0; it < 32; it++) {
            int idx = tid + it * 256;
            int r = idx >> 5;
            int w = idx & 31;
            Bh[r * 36 + w] = Bhi[r * 64 + kc * 32 + w];
            Bl[r * 36 + w] = Blo[r * 64 + kc * 32 + w];
        }
        __syncthreads();

        #pragma unroll
        for (int ksl = 0; ksl < 4; ksl++) {
            uint32_t kb = (uint32_t)((kc * 32 + ksl * 8) * 4);   // A k-word offset, bytes
            uint32_t bb = (uint32_t)((ksl * 8) * 4);             // B k-word offset, bytes
            uint32_t ah[2][4], al[2][4];
            ldsm_x4(ah[0], ah_base + kb);
            ldsm_x4(ah[1], ah_base + kb + 16 * 68 * 4);
            ldsm_x4(al[0], al_base + kb);
            ldsm_x4(al[1], al_base + kb + 16 * 68 * 4);
            // products 1 & 2: (Ah + Al) * Bh
            #pragma unroll
            for (int q = 0; q < 4; q++) {
                uint32_t bf[4];
                ldsm_x4(bf, bh_base + bb + (uint32_t)(q * 16 * 36 * 4));
                mma_bf16(acc[0][2 * q],     ah[0], bf[0], bf[1]);
                mma_bf16(acc[1][2 * q],     ah[1], bf[0], bf[1]);
                mma_bf16(acc[0][2 * q + 1], ah[0], bf[2], bf[3]);
                mma_bf16(acc[1][2 * q + 1], ah[1], bf[2], bf[3]);
                mma_bf16(acc[0][2 * q],     al[0], bf[0], bf[1]);
                mma_bf16(acc[1][2 * q],     al[1], bf[0], bf[1]);
                mma_bf16(acc[0][2 * q + 1], al[0], bf[2], bf[3]);
                mma_bf16(acc[1][2 * q + 1], al[1], bf[2], bf[3]);
            }
            // product 3: Ah * Bl
            #pragma unroll
            for (int q = 0; q < 4; q++) {
                uint32_t bf[4];
                ldsm_x4(bf, bl_base + bb + (uint32_t)(q * 16 * 36 * 4));
                mma_bf16(acc[0][2 * q],     ah[0], bf[0], bf[1]);
                mma_bf16(acc[1][2 * q],     ah[1], bf[0], bf[1]);
                mma_bf16(acc[0][2 * q + 1], ah[0], bf[2], bf[3]);
                mma_bf16(acc[1][2 * q + 1], ah[1], bf[2], bf[3]);
            }
        }
    }

    int gr0 = row0 + mloc;
    if (ni < 2) {
        float ps[2][2][2], pd[2][2][2];
        #pragma unroll
        for (int a = 0; a < 2; a++)
            #pragma unroll
            for (int b = 0; b < 2; b++) {
                ps[a][b][0] = ps[a][b][1] = 0.f;
                pd[a][b][0] = pd[a][b][1] = 0.f;
            }
        #pragma unroll
        for (int mt = 0; mt < 2; mt++) {
            int r0 = gr0 + mt * 16 + g;
            int r1 = r0 + 8;
            #pragma unroll
            for (int nt = 0; nt < 8; nt++) {
                int col = nbase + nt * 8 + t * 2;
                int hh = nt >> 2;
                float s0 = s_att[col],       s1 = s_att[col + 1];
                float d0 = s_att[128 + col], d1 = s_att[128 + col + 1];
                ps[mt][0][hh] += acc[mt][nt][0] * s0 + acc[mt][nt][1] * s1;
                pd[mt][0][hh] += acc[mt][nt][0] * d0 + acc[mt][nt][1] * d1;
                ps[mt][1][hh] += acc[mt][nt][2] * s0 + acc[mt][nt][3] * s1;
                pd[mt][1][hh] += acc[mt][nt][2] * d0 + acc[mt][nt][3] * d1;
                if (r0 < nrows)
                    *(float2*)(g_h + (size_t)r0 * 128 + col) =
                        make_float2(acc[mt][nt][0], acc[mt][nt][1]);
                if (r1 < nrows)
                    *(float2*)(g_h + (size_t)r1 * 128 + col) =
                        make_float2(acc[mt][nt][2], acc[mt][nt][3]);
            }
        }
        #pragma unroll
        for (int mt = 0; mt < 2; mt++)
            #pragma unroll
            for (int rs = 0; rs < 2; rs++)
                #pragma unroll
                for (int hh = 0; hh < 2; hh++) {
                    float vs = ps[mt][rs][hh];
                    float vd = pd[mt][rs][hh];
                    vs += __shfl_xor_sync(0xffffffffu, vs, 1);
                    vs += __shfl_xor_sync(0xffffffffu, vs, 2);
                    vd += __shfl_xor_sync(0xffffffffu, vd, 1);
                    vd += __shfl_xor_sync(0xffffffffu, vd, 2);
                    if (t == 0) {
                        int r = gr0 + mt * 16 + g + rs * 8;
                        if (r < nrows) {
                            int head = ni * 2 + hh;
                            g_asrc[r * 4 + head] = vs;
                            g_adst[r * 4 + head] = vd;
                        }
                    }
                }
    } else {
        int cb = nbase - 128;
        #pragma unroll
        for (int mt = 0; mt < 2; mt++) {
            int r0 = gr0 + mt * 16 + g;
            int r1 = r0 + 8;
            #pragma unroll
            for (int nt = 0; nt < 8; nt++) {
                int col = cb + nt * 8 + t * 2;
                if (r0 < nrows)
                    *(float2*)(g_skip + (size_t)r0 * 128 + col) =
                        make_float2(acc[mt][nt][0], acc[mt][nt][1]);
                if (r1 < nrows)
                    *(float2*)(g_skip + (size_t)r1 * 128 + col) =
                        make_float2(acc[mt][nt][2], acc[mt][nt][3]);
            }
        }
    }
}

// ------------------- online-softmax aggregate, 4-edge batched loads -------------------
__global__ void __launch_bounds__(256)
agg_kernel(const float* __restrict__ bias, float* __restrict__ out, int N) {
    int gw = (blockIdx.x * blockDim.x + threadIdx.x) >> 5;
    int lane = threadIdx.x & 31;
    if (gw >= N) return;
    int n = gw;
    int beg = g_off[n];
    int end = g_off[n + 1];
    int head = lane >> 3;

    float adh = g_adst[n * 4 + head];
    const float4* h4 = (const float4*)g_h;

    float m = -INFINITY;
    float denom = 0.0f;
    float4 acc = make_float4(0.f, 0.f, 0.f, 0.f);

    int j = beg;
    for (; j + 4 <= end; j += 4) {
        int s0 = g_csr[j];
        int s1 = g_csr[j + 1];
        int s2 = g_csr[j + 2];
        int s3 = g_csr[j + 3];
        float a0 = g_asrc[s0 * 4 + head];
        float a1 = g_asrc[s1 * 4 + head];
        float a2 = g_asrc[s2 * 4 + head];
        float a3 = g_asrc[s3 * 4 + head];
        float4 v0 = h4[(size_t)s0 * 32 + lane];
        float4 v1 = h4[(size_t)s1 * 32 + lane];
        float4 v2 = h4[(size_t)s2 * 32 + lane];
        float4 v3 = h4[(size_t)s3 * 32 + lane];

        float e0 = a0 + adh; e0 = (e0 > 0.f) ? e0 : NEG_SLOPE * e0;
        float e1 = a1 + adh; e1 = (e1 > 0.f) ? e1 : NEG_SLOPE * e1;
        float e2 = a2 + adh; e2 = (e2 > 0.f) ? e2 : NEG_SLOPE * e2;
        float e3 = a3 + adh; e3 = (e3 > 0.f) ? e3 : NEG_SLOPE * e3;

        float mx = fmaxf(fmaxf(e0, e1), fmaxf(e2, e3));
        if (mx > m) {
            float sc = __expf(m - mx);
            denom *= sc;
            acc.x *= sc; acc.y *= sc; acc.z *= sc; acc.w *= sc;
            m = mx;
        }
        float w0 = __expf(e0 - m);
        float w1 = __expf(e1 - m);
        float w2 = __expf(e2 - m);
        float w3 = __expf(e3 - m);
        denom += (w0 + w1) + (w2 + w3);
        acc.x += w0 * v0.x + w1 * v1.x + w2 * v2.x + w3 * v3.x;
        acc.y += w0 * v0.y + w1 * v1.y + w2 * v2.y + w3 * v3.y;
        acc.z += w0 * v0.z + w1 * v1.z + w2 * v2.z + w3 * v3.z;
        acc.w += w0 * v0.w + w1 * v1.w + w2 * v2.w + w3 * v3.w;
    }
    for (; j < end; j++) {
        int s = g_csr[j];
        float a = g_asrc[s * 4 + head];
        float e = a + adh; e = (e > 0.f) ? e : NEG_SLOPE * e;
        float4 v = h4[(size_t)s * 32 + lane];
        if (e > m) {
            float sc = __expf(m - e);
            denom *= sc;
            acc.x *= sc; acc.y *= sc; acc.z *= sc; acc.w *= sc;
            m = e;
        }
        float w = __expf(e - m);
        denom += w;
        acc.x += w * v.x; acc.y += w * v.y; acc.z += w * v.z; acc.w += w * v.w;
    }

    float inv = 1.0f / (denom + 1e-16f);
    float4 b  = ((const float4*)bias)[lane];
    float4 sk = ((const float4*)g_skip)[(size_t)n * 32 + lane];
    float4 o;
    o.x = acc.x * inv + b.x + sk.x;
    o.y = acc.y * inv + b.y + sk.y;
    o.z = acc.z * inv + b.z + sk.z;
    o.w = acc.w * inv + b.w + sk.w;
    o.x = (o.x > 0.f) ? o.x : expm1f(o.x);
    o.y = (o.y > 0.f) ? o.y : expm1f(o.y);
    o.z = (o.z > 0.f) ? o.z : expm1f(o.z);
    o.w = (o.w > 0.f) ? o.w : expm1f(o.w);
    ((float4*)out)[(size_t)n * 32 + lane] = o;
}

// ------------------- launch -------------------
extern "C" void kernel_launch(void* const* d_in, const int* in_sizes, int n_in,
                              void* d_out, int out_size) {
    const float* x    = (const float*)d_in[0];
    const int*   ei   = (const int*)  d_in[1];
    const float* W1   = (const float*)d_in[2];
    const float* as1  = (const float*)d_in[3];
    const float* ad1  = (const float*)d_in[4];
    const float* b1   = (const float*)d_in[5];
    const float* Ws1  = (const float*)d_in[6];
    const float* W2   = (const float*)d_in[7];
    const float* as2  = (const float*)d_in[8];
    const float* ad2  = (const float*)d_in[9];
    const float* b2   = (const float*)d_in[10];
    const float* Ws2  = (const float*)d_in[11];

    int N = in_sizes[0] / DIM;
    int E = in_sizes[1] / 2;
    const int* src = ei;
    const int* dst = ei + E;

    float* buf1;  cudaGetSymbolAddress((void**)&buf1, g_buf1);
    __nv_bfloat16* bhi; cudaGetSymbolAddress((void**)&bhi, g_bhi);
    __nv_bfloat16* blo; cudaGetSymbolAddress((void**)&blo, g_blo);

    const size_t dyn = 27136 * 4;
    cudaFuncSetAttribute(gat_mma_fused, cudaFuncAttributeMaxDynamicSharedMemorySize, (int)dyn);

    int nb = (N + SCAN_CHUNK - 1) / SCAN_CHUNK;
    int gemm_blocks = (N + 63) / 64;
    int warp_blocks = (N * 32 + 255) / 256;

    // GEMM stays at launch index 3 (profiled slot) to verify the ldmatrix delta.
    prep_hist<<<WPREP_BLKS + 1024, 256>>>(W1, Ws1, W2, Ws2, dst, E);       // 0
    scan_lookback<<<nb, 256>>>(N);                                         // 1
    scatter_kernel<<<(E + N + 255) / 256, 256>>>(src, dst, E, N);          // 2
    gat_mma_fused<<<gemm_blocks, 256, dyn>>>(                              // 3 <- profiled
        x, (const uint32_t*)bhi, (const uint32_t*)blo, as1, ad1, N);
    agg_kernel<<<warp_blocks, 256>>>(b1, buf1, N);                         // 4
    gat_mma_fused<<<gemm_blocks, 256, dyn>>>(                              // 5
        buf1, (const uint32_t*)(bhi + 256 * 128), (const uint32_t*)(blo + 256 * 128),
        as2, ad2, N);
    agg_kernel<<<warp_blocks, 256>>>(b2, (float*)d_out, N);                // 6
}

// round 11
// speedup vs baseline: 1.1643x; 1.0014x over previous
#include <cuda_runtime.h>
#include <cuda_bf16.h>
#include <stdint.h>
#include <math.h>

#define DIM 128
#define HEADS 4
#define NEG_SLOPE 0.2f
#define MAX_N 50000
#define MAX_E 600000
#define SCAN_CHUNK 1024
#define MAX_NB ((MAX_N + SCAN_CHUNK - 1) / SCAN_CHUNK)
#define WPREP_BLKS 256   // 65536 weight elems / 256 thr

// ------------------- scratch (static device globals; no allocs) -------------------
__device__ float g_h[MAX_N * DIM];
__device__ float g_skip[MAX_N * DIM];
__device__ float g_buf1[MAX_N * DIM];
__device__ float g_asrc[MAX_N * HEADS];
__device__ float g_adst[MAX_N * HEADS];
__device__ int   g_deg[MAX_N];           // zero-invariant: scan re-zeroes after read
__device__ int   g_off[MAX_N + 1];
__device__ int   g_cursor[MAX_N];
__device__ int   g_csr[MAX_E + MAX_N];
__device__ int   g_agg[MAX_NB];
__device__ int   g_flag[MAX_NB];         // zero-invariant: scatter re-zeroes
// combined transposed weights per layer: Bt[n][k]: n<128 -> W[k][n], else Wskip[k][n-128]
__device__ __nv_bfloat16 g_bhi[2 * 256 * 128];
__device__ __nv_bfloat16 g_blo[2 * 256 * 128];

// ------------------- prep (weights) + degree histogram, role-split -------------------
__global__ void prep_hist(const float* __restrict__ W1, const float* __restrict__ Ws1,
                          const float* __restrict__ W2, const float* __restrict__ Ws2,
                          const int* __restrict__ dst, int E) {
    int tid = threadIdx.x;
    if ((int)blockIdx.x < WPREP_BLKS) {
        int idx = blockIdx.x * 256 + tid;                 // 0..65535
        int layer = idx >> 15;
        int rem   = idx & 32767;
        int n     = rem >> 7;
        int k     = rem & 127;
        const float* W = layer ? (n < 128 ? W2 : Ws2) : (n < 128 ? W1 : Ws1);
        float v = W[k * 128 + (n & 127)];
        __nv_bfloat16 hi = __float2bfloat16(v);
        float lo = v - __bfloat162float(hi);
        g_bhi[idx] = hi;
        g_blo[idx] = __float2bfloat16(lo);
    } else {
        int nbh = gridDim.x - WPREP_BLKS;
        for (int i = (blockIdx.x - WPREP_BLKS) * 256 + tid; i < E; i += nbh * 256)
            atomicAdd(&g_deg[dst[i]], 1);
    }
}

// ------------------- single-kernel scan with decoupled lookback -------------------
__global__ void scan_lookback(int N) {
    __shared__ int wsum[8];
    __shared__ int s_base;
    int tid = threadIdx.x;
    int lane = tid & 31, warp = tid >> 5;
    int b = blockIdx.x;
    int i0 = b * SCAN_CHUNK + tid * 4;

    int4 d = make_int4(0, 0, 0, 0);
    if (i0 + 3 < N) {
        d = *(const int4*)(g_deg + i0);
        *(int4*)(g_deg + i0) = make_int4(0, 0, 0, 0);
        d.x += 1; d.y += 1; d.z += 1; d.w += 1;   // self-loops
    } else {
        if (i0 + 0 < N) { d.x = g_deg[i0 + 0] + 1; g_deg[i0 + 0] = 0; }
        if (i0 + 1 < N) { d.y = g_deg[i0 + 1] + 1; g_deg[i0 + 1] = 0; }
        if (i0 + 2 < N) { d.z = g_deg[i0 + 2] + 1; g_deg[i0 + 2] = 0; }
        if (i0 + 3 < N) { d.w = g_deg[i0 + 3] + 1; g_deg[i0 + 3] = 0; }
    }
    int T = d.x + d.y + d.z + d.w;
    int v = T;
    #pragma unroll
    for (int o = 1; o < 32; o <<= 1) {
        int t = __shfl_up_sync(0xffffffffu, v, o);
        if (lane >= o) v += t;
    }
    if (lane == 31) wsum[warp] = v;
    __syncthreads();
    if (warp == 0) {
        int w = (lane < 8) ? wsum[lane] : 0;
        #pragma unroll
        for (int o = 1; o < 8; o <<= 1) {
            int t = __shfl_up_sync(0xffffffffu, w, o);
            if (lane >= o) w += t;
        }
        if (lane < 8) wsum[lane] = w;
        if (lane == 0) {
            g_agg[b] = wsum[7];
            __threadfence();
            atomicExch(&g_flag[b], 1);
        }
    }
    __syncthreads();
    int blk_scan = (warp ? wsum[warp - 1] : 0);

    if (warp == 0) {
        int base = 0;
        for (int i = lane; i < b; i += 32) {
            while (atomicAdd(&g_flag[i], 0) == 0) {}
            base += g_agg[i];
        }
        #pragma unroll
        for (int o = 16; o > 0; o >>= 1) base += __shfl_xor_sync(0xffffffffu, base, o);
        if (lane == 0) s_base = base;
    }
    __syncthreads();

    int excl = v - T + blk_scan + s_base;
    int p = excl;
    if (i0 + 0 < N) { g_cursor[i0 + 0] = p; g_off[i0 + 1] = p + d.x; p += d.x; }
    if (i0 + 1 < N) { g_cursor[i0 + 1] = p; g_off[i0 + 2] = p + d.y; p += d.y; }
    if (i0 + 2 < N) { g_cursor[i0 + 2] = p; g_off[i0 + 3] = p + d.z; p += d.z; }
    if (i0 + 3 < N) { g_cursor[i0 + 3] = p; g_off[i0 + 4] = p + d.w; }
    if (b == 0 && tid == 0) g_off[0] = 0;
}

__global__ void scatter_kernel(const int* __restrict__ src, const int* __restrict__ dst,
                               int E, int N) {
    int i = blockIdx.x * blockDim.x + threadIdx.x;
    if (i < MAX_NB) g_flag[i] = 0;   // reset lookback flags for next replay
    if (i < E) {
        int d = dst[i];
        int p = atomicAdd(&g_cursor[d], 1);
        g_csr[p] = src[i];
    } else if (i < E + N) {
        int n = i - E;
        int p = atomicAdd(&g_cursor[n], 1);
        g_csr[p] = n;
    }
}

// ------------------- MMA / ldmatrix helpers -------------------
__device__ __forceinline__ void mma_bf16(float c[4], const uint32_t a[4],
                                         uint32_t b0, uint32_t b1) {
    asm volatile(
        "mma.sync.aligned.m16n8k16.row.col.f32.bf16.bf16.f32 "
        "{%0,%1,%2,%3}, {%4,%5,%6,%7}, {%8,%9}, {%0,%1,%2,%3};"
        : "+f"(c[0]), "+f"(c[1]), "+f"(c[2]), "+f"(c[3])
        : "r"(a[0]), "r"(a[1]), "r"(a[2]), "r"(a[3]), "r"(b0), "r"(b1));
}
__device__ __forceinline__ void ldsm_x4(uint32_t d[4], uint32_t addr) {
    asm volatile("ldmatrix.sync.aligned.m8n8.x4.shared.b16 {%0,%1,%2,%3}, [%4];"
                 : "=r"(d[0]), "=r"(d[1]), "=r"(d[2]), "=r"(d[3]) : "r"(addr));
}
__device__ __forceinline__ uint32_t s2u(const void* p) {
    return (uint32_t)__cvta_generic_to_shared(p);
}

// ------------------- fused HMMA GEMM (h + skip) + attention logits -------------------
// Product-major MMA order per k-step: 16 distinct-acc MMAs per product -> RAW distance 16.
__global__ void __launch_bounds__(256, 2)
gat_mma_fused(const float* __restrict__ X,
              const uint32_t* __restrict__ Bhi, const uint32_t* __restrict__ Blo,
              const float* __restrict__ a_src, const float* __restrict__ a_dst,
              int nrows) {
    extern __shared__ uint32_t dsm[];
    __shared__ float s_att[256];
    uint32_t* Ah = dsm;            // 64*68
    uint32_t* Al = dsm + 4352;
    uint32_t* Bh = dsm + 8704;     // 256*36
    uint32_t* Bl = dsm + 17920;

    int tid  = threadIdx.x;
    int row0 = blockIdx.x * 64;
    if (tid < 128) { s_att[tid] = a_src[tid]; s_att[128 + tid] = a_dst[tid]; }

    #pragma unroll
    for (int it = 0; it < 16; it++) {
        int idx = tid + it * 256;
        int r = idx >> 6;
        int w = idx & 63;
        float x0 = 0.f, x1 = 0.f;
        int gr = row0 + r;
        if (gr < nrows) {
            float2 v = *(const float2*)(X + (size_t)gr * 128 + w * 2);
            x0 = v.x; x1 = v.y;
        }
        __nv_bfloat16 h0 = __float2bfloat16(x0);
        __nv_bfloat16 h1 = __float2bfloat16(x1);
        __nv_bfloat16 l0 = __float2bfloat16(x0 - __bfloat162float(h0));
        __nv_bfloat16 l1 = __float2bfloat16(x1 - __bfloat162float(h1));
        Ah[r * 68 + w] = ((uint32_t)__bfloat16_as_ushort(h1) << 16) | __bfloat16_as_ushort(h0);
        Al[r * 68 + w] = ((uint32_t)__bfloat16_as_ushort(l1) << 16) | __bfloat16_as_ushort(l0);
    }

    int lane = tid & 31, warp = tid >> 5;
    int mi = warp & 1, ni = warp >> 1;
    int g = lane >> 2, t = lane & 3;
    int mloc  = mi * 32;
    int nbase = ni * 64;

    // per-lane ldmatrix address offsets (bytes)
    uint32_t a_off = (uint32_t)(((mloc + (lane & 15)) * 68 + ((lane >> 4) << 2)) * 4);
    uint32_t ah_base = s2u(Ah) + a_off;
    uint32_t al_base = s2u(Al) + a_off;
    uint32_t b_off = (uint32_t)((((nbase + ((lane >> 4) << 3) + (lane & 7)) * 36)
                                 + (((lane >> 3) & 1) << 2)) * 4);
    uint32_t bh_base = s2u(Bh) + b_off;
    uint32_t bl_base = s2u(Bl) + b_off;

    float acc[2][8][4];
    #pragma unroll
    for (int a = 0; a < 2; a++)
        #pragma unroll
        for (int b = 0; b < 8; b++)
            #pragma unroll
            for (int c = 0; c < 4; c++) acc[a][b][c] = 0.f;

    for (int kc = 0; kc < 2; kc++) {
        if (kc) __syncthreads();
        #pragma unroll
        for (int it = 0; it < 32; it++) {
            int idx = tid + it * 256;
            int r = idx >> 5;
            int w = idx & 31;
            Bh[r * 36 + w] = Bhi[r * 64 + kc * 32 + w];
            Bl[r * 36 + w] = Blo[r * 64 + kc * 32 + w];
        }
        __syncthreads();

        #pragma unroll
        for (int ksl = 0; ksl < 4; ksl++) {
            uint32_t kb = (uint32_t)((kc * 32 + ksl * 8) * 4);   // A k-word offset, bytes
            uint32_t bb = (uint32_t)((ksl * 8) * 4);             // B k-word offset, bytes
            uint32_t ah[2][4], al[2][4], bf[4][4];
            ldsm_x4(ah[0], ah_base + kb);
            ldsm_x4(ah[1], ah_base + kb + 16 * 68 * 4);
            ldsm_x4(al[0], al_base + kb);
            ldsm_x4(al[1], al_base + kb + 16 * 68 * 4);
            #pragma unroll
            for (int q = 0; q < 4; q++)
                ldsm_x4(bf[q], bh_base + bb + (uint32_t)(q * 16 * 36 * 4));
            // product 1: Ah*Bh — 16 MMAs, all distinct accumulators
            #pragma unroll
            for (int q = 0; q < 4; q++) {
                mma_bf16(acc[0][2 * q],     ah[0], bf[q][0], bf[q][1]);
                mma_bf16(acc[1][2 * q],     ah[1], bf[q][0], bf[q][1]);
                mma_bf16(acc[0][2 * q + 1], ah[0], bf[q][2], bf[q][3]);
                mma_bf16(acc[1][2 * q + 1], ah[1], bf[q][2], bf[q][3]);
            }
            // product 2: Al*Bh — 16 MMAs, distinct accs (RAW distance 16 vs product 1)
            #pragma unroll
            for (int q = 0; q < 4; q++) {
                mma_bf16(acc[0][2 * q],     al[0], bf[q][0], bf[q][1]);
                mma_bf16(acc[1][2 * q],     al[1], bf[q][0], bf[q][1]);
                mma_bf16(acc[0][2 * q + 1], al[0], bf[q][2], bf[q][3]);
                mma_bf16(acc[1][2 * q + 1], al[1], bf[q][2], bf[q][3]);
            }
            // product 3: Ah*Bl — reload B frags, 16 MMAs
            #pragma unroll
            for (int q = 0; q < 4; q++)
                ldsm_x4(bf[q], bl_base + bb + (uint32_t)(q * 16 * 36 * 4));
            #pragma unroll
            for (int q = 0; q < 4; q++) {
                mma_bf16(acc[0][2 * q],     ah[0], bf[q][0], bf[q][1]);
                mma_bf16(acc[1][2 * q],     ah[1], bf[q][0], bf[q][1]);
                mma_bf16(acc[0][2 * q + 1], ah[0], bf[q][2], bf[q][3]);
                mma_bf16(acc[1][2 * q + 1], ah[1], bf[q][2], bf[q][3]);
            }
        }
    }

    int gr0 = row0 + mloc;
    if (ni < 2) {
        float ps[2][2][2], pd[2][2][2];
        #pragma unroll
        for (int a = 0; a < 2; a++)
            #pragma unroll
            for (int b = 0; b < 2; b++) {
                ps[a][b][0] = ps[a][b][1] = 0.f;
                pd[a][b][0] = pd[a][b][1] = 0.f;
            }
        #pragma unroll
        for (int mt = 0; mt < 2; mt++) {
            int r0 = gr0 + mt * 16 + g;
            int r1 = r0 + 8;
            #pragma unroll
            for (int nt = 0; nt < 8; nt++) {
                int col = nbase + nt * 8 + t * 2;
                int hh = nt >> 2;
                float s0 = s_att[col],       s1 = s_att[col + 1];
                float d0 = s_att[128 + col], d1 = s_att[128 + col + 1];
                ps[mt][0][hh] += acc[mt][nt][0] * s0 + acc[mt][nt][1] * s1;
                pd[mt][0][hh] += acc[mt][nt][0] * d0 + acc[mt][nt][1] * d1;
                ps[mt][1][hh] += acc[mt][nt][2] * s0 + acc[mt][nt][3] * s1;
                pd[mt][1][hh] += acc[mt][nt][2] * d0 + acc[mt][nt][3] * d1;
                if (r0 < nrows)
                    *(float2*)(g_h + (size_t)r0 * 128 + col) =
                        make_float2(acc[mt][nt][0], acc[mt][nt][1]);
                if (r1 < nrows)
                    *(float2*)(g_h + (size_t)r1 * 128 + col) =
                        make_float2(acc[mt][nt][2], acc[mt][nt][3]);
            }
        }
        #pragma unroll
        for (int mt = 0; mt < 2; mt++)
            #pragma unroll
            for (int rs = 0; rs < 2; rs++)
                #pragma unroll
                for (int hh = 0; hh < 2; hh++) {
                    float vs = ps[mt][rs][hh];
                    float vd = pd[mt][rs][hh];
                    vs += __shfl_xor_sync(0xffffffffu, vs, 1);
                    vs += __shfl_xor_sync(0xffffffffu, vs, 2);
                    vd += __shfl_xor_sync(0xffffffffu, vd, 1);
                    vd += __shfl_xor_sync(0xffffffffu, vd, 2);
                    if (t == 0) {
                        int r = gr0 + mt * 16 + g + rs * 8;
                        if (r < nrows) {
                            int head = ni * 2 + hh;
                            g_asrc[r * 4 + head] = vs;
                            g_adst[r * 4 + head] = vd;
                        }
                    }
                }
    } else {
        int cb = nbase - 128;
        #pragma unroll
        for (int mt = 0; mt < 2; mt++) {
            int r0 = gr0 + mt * 16 + g;
            int r1 = r0 + 8;
            #pragma unroll
            for (int nt = 0; nt < 8; nt++) {
                int col = cb + nt * 8 + t * 2;
                if (r0 < nrows)
                    *(float2*)(g_skip + (size_t)r0 * 128 + col) =
                        make_float2(acc[mt][nt][0], acc[mt][nt][1]);
                if (r1 < nrows)
                    *(float2*)(g_skip + (size_t)r1 * 128 + col) =
                        make_float2(acc[mt][nt][2], acc[mt][nt][3]);
            }
        }
    }
}

// ------------------- online-softmax aggregate, 4-edge batched loads -------------------
__global__ void __launch_bounds__(256)
agg_kernel(const float* __restrict__ bias, float* __restrict__ out, int N) {
    int gw = (blockIdx.x * blockDim.x + threadIdx.x) >> 5;
    int lane = threadIdx.x & 31;
    if (gw >= N) return;
    int n = gw;
    int beg = g_off[n];
    int end = g_off[n + 1];
    int head = lane >> 3;

    float adh = g_adst[n * 4 + head];
    const float4* h4 = (const float4*)g_h;

    float m = -INFINITY;
    float denom = 0.0f;
    float4 acc = make_float4(0.f, 0.f, 0.f, 0.f);

    int j = beg;
    for (; j + 4 <= end; j += 4) {
        int s0 = g_csr[j];
        int s1 = g_csr[j + 1];
        int s2 = g_csr[j + 2];
        int s3 = g_csr[j + 3];
        float a0 = g_asrc[s0 * 4 + head];
        float a1 = g_asrc[s1 * 4 + head];
        float a2 = g_asrc[s2 * 4 + head];
        float a3 = g_asrc[s3 * 4 + head];
        float4 v0 = h4[(size_t)s0 * 32 + lane];
        float4 v1 = h4[(size_t)s1 * 32 + lane];
        float4 v2 = h4[(size_t)s2 * 32 + lane];
        float4 v3 = h4[(size_t)s3 * 32 + lane];

        float e0 = a0 + adh; e0 = (e0 > 0.f) ? e0 : NEG_SLOPE * e0;
        float e1 = a1 + adh; e1 = (e1 > 0.f) ? e1 : NEG_SLOPE * e1;
        float e2 = a2 + adh; e2 = (e2 > 0.f) ? e2 : NEG_SLOPE * e2;
        float e3 = a3 + adh; e3 = (e3 > 0.f) ? e3 : NEG_SLOPE * e3;

        float mx = fmaxf(fmaxf(e0, e1), fmaxf(e2, e3));
        if (mx > m) {
            float sc = __expf(m - mx);
            denom *= sc;
            acc.x *= sc; acc.y *= sc; acc.z *= sc; acc.w *= sc;
            m = mx;
        }
        float w0 = __expf(e0 - m);
        float w1 = __expf(e1 - m);
        float w2 = __expf(e2 - m);
        float w3 = __expf(e3 - m);
        denom += (w0 + w1) + (w2 + w3);
        acc.x += w0 * v0.x + w1 * v1.x + w2 * v2.x + w3 * v3.x;
        acc.y += w0 * v0.y + w1 * v1.y + w2 * v2.y + w3 * v3.y;
        acc.z += w0 * v0.z + w1 * v1.z + w2 * v2.z + w3 * v3.z;
        acc.w += w0 * v0.w + w1 * v1.w + w2 * v2.w + w3 * v3.w;
    }
    for (; j < end; j++) {
        int s = g_csr[j];
        float a = g_asrc[s * 4 + head];
        float e = a + adh; e = (e > 0.f) ? e : NEG_SLOPE * e;
        float4 v = h4[(size_t)s * 32 + lane];
        if (e > m) {
            float sc = __expf(m - e);
            denom *= sc;
            acc.x *= sc; acc.y *= sc; acc.z *= sc; acc.w *= sc;
            m = e;
        }
        float w = __expf(e - m);
        denom += w;
        acc.x += w * v.x; acc.y += w * v.y; acc.z += w * v.z; acc.w += w * v.w;
    }

    float inv = 1.0f / (denom + 1e-16f);
    float4 b  = ((const float4*)bias)[lane];
    float4 sk = ((const float4*)g_skip)[(size_t)n * 32 + lane];
    float4 o;
    o.x = acc.x * inv + b.x + sk.x;
    o.y = acc.y * inv + b.y + sk.y;
    o.z = acc.z * inv + b.z + sk.z;
    o.w = acc.w * inv + b.w + sk.w;
    o.x = (o.x > 0.f) ? o.x : expm1f(o.x);
    o.y = (o.y > 0.f) ? o.y : expm1f(o.y);
    o.z = (o.z > 0.f) ? o.z : expm1f(o.z);
    o.w = (o.w > 0.f) ? o.w : expm1f(o.w);
    ((float4*)out)[(size_t)n * 32 + lane] = o;
}

// ------------------- launch -------------------
extern "C" void kernel_launch(void* const* d_in, const int* in_sizes, int n_in,
                              void* d_out, int out_size) {
    const float* x    = (const float*)d_in[0];
    const int*   ei   = (const int*)  d_in[1];
    const float* W1   = (const float*)d_in[2];
    const float* as1  = (const float*)d_in[3];
    const float* ad1  = (const float*)d_in[4];
    const float* b1   = (const float*)d_in[5];
    const float* Ws1  = (const float*)d_in[6];
    const float* W2   = (const float*)d_in[7];
    const float* as2  = (const float*)d_in[8];
    const float* ad2  = (const float*)d_in[9];
    const float* b2   = (const float*)d_in[10];
    const float* Ws2  = (const float*)d_in[11];

    int N = in_sizes[0] / DIM;
    int E = in_sizes[1] / 2;
    const int* src = ei;
    const int* dst = ei + E;

    float* buf1;  cudaGetSymbolAddress((void**)&buf1, g_buf1);
    __nv_bfloat16* bhi; cudaGetSymbolAddress((void**)&bhi, g_bhi);
    __nv_bfloat16* blo; cudaGetSymbolAddress((void**)&blo, g_blo);

    const size_t dyn = 27136 * 4;
    cudaFuncSetAttribute(gat_mma_fused, cudaFuncAttributeMaxDynamicSharedMemorySize, (int)dyn);

    int nb = (N + SCAN_CHUNK - 1) / SCAN_CHUNK;
    int gemm_blocks = (N + 63) / 64;
    int warp_blocks = (N * 32 + 255) / 256;

    // GEMM stays at launch index 3 (profiled slot) to verify the reorder delta.
    prep_hist<<<WPREP_BLKS + 1024, 256>>>(W1, Ws1, W2, Ws2, dst, E);       // 0
    scan_lookback<<<nb, 256>>>(N);                                         // 1
    scatter_kernel<<<(E + N + 255) / 256, 256>>>(src, dst, E, N);          // 2
    gat_mma_fused<<<gemm_blocks, 256, dyn>>>(                              // 3 <- profiled
        x, (const uint32_t*)bhi, (const uint32_t*)blo, as1, ad1, N);
    agg_kernel<<<warp_blocks, 256>>>(b1, buf1, N);                         // 4
    gat_mma_fused<<<gemm_blocks, 256, dyn>>>(                              // 5
        buf1, (const uint32_t*)(bhi + 256 * 128), (const uint32_t*)(blo + 256 * 128),
        as2, ad2, N);
    agg_kernel<<<warp_blocks, 256>>>(b2, (float*)d_out, N);                // 6
}

// round 12
// speedup vs baseline: 1.1743x; 1.0086x over previous
#include <cuda_runtime.h>
#include <cuda_bf16.h>
#include <cuda_fp16.h>
#include <stdint.h>
#include <math.h>

#define DIM 128
#define HEADS 4
#define NEG_SLOPE 0.2f
#define MAX_N 50000
#define MAX_E 600000
#define SCAN_CHUNK 1024
#define MAX_NB ((MAX_N + SCAN_CHUNK - 1) / SCAN_CHUNK)
#define WPREP_BLKS 256   // 65536 weight elems / 256 thr
#define SCAT_BLKS 1024   // scatter-role blocks appended to GEMM-1

// ------------------- scratch (static device globals; no allocs) -------------------
__device__ __half2 g_hh[MAX_N * 64];     // transformed features (fp16 message payload)
__device__ float g_skip[MAX_N * DIM];
__device__ float g_buf1[MAX_N * DIM];
__device__ float g_asrc[MAX_N * HEADS];
__device__ float g_adst[MAX_N * HEADS];
__device__ int   g_deg[MAX_N];           // zero-invariant: scan re-zeroes after read
__device__ int   g_off[MAX_N + 1];
__device__ int   g_cursor[MAX_N];
__device__ int   g_csr[MAX_E + MAX_N];
__device__ int   g_agg[MAX_NB];
__device__ int   g_flag[MAX_NB];         // zero-invariant: scatter role re-zeroes
// combined transposed weights per layer: Bt[n][k]: n<128 -> W[k][n], else Wskip[k][n-128]
__device__ __nv_bfloat16 g_bhi[2 * 256 * 128];
__device__ __nv_bfloat16 g_blo[2 * 256 * 128];

// ------------------- prep (weights) + degree histogram, role-split -------------------
__global__ void prep_hist(const float* __restrict__ W1, const float* __restrict__ Ws1,
                          const float* __restrict__ W2, const float* __restrict__ Ws2,
                          const int* __restrict__ dst, int E) {
    int tid = threadIdx.x;
    if ((int)blockIdx.x < WPREP_BLKS) {
        int idx = blockIdx.x * 256 + tid;                 // 0..65535
        int layer = idx >> 15;
        int rem   = idx & 32767;
        int n     = rem >> 7;
        int k     = rem & 127;
        const float* W = layer ? (n < 128 ? W2 : Ws2) : (n < 128 ? W1 : Ws1);
        float v = W[k * 128 + (n & 127)];
        __nv_bfloat16 hi = __float2bfloat16(v);
        float lo = v - __bfloat162float(hi);
        g_bhi[idx] = hi;
        g_blo[idx] = __float2bfloat16(lo);
    } else {
        int nbh = gridDim.x - WPREP_BLKS;
        for (int i = (blockIdx.x - WPREP_BLKS) * 256 + tid; i < E; i += nbh * 256)
            atomicAdd(&g_deg[dst[i]], 1);
    }
}

// ------------------- single-kernel scan with decoupled lookback -------------------
__global__ void scan_lookback(int N) {
    __shared__ int wsum[8];
    __shared__ int s_base;
    int tid = threadIdx.x;
    int lane = tid & 31, warp = tid >> 5;
    int b = blockIdx.x;
    int i0 = b * SCAN_CHUNK + tid * 4;

    int4 d = make_int4(0, 0, 0, 0);
    if (i0 + 3 < N) {
        d = *(const int4*)(g_deg + i0);
        *(int4*)(g_deg + i0) = make_int4(0, 0, 0, 0);
        d.x += 1; d.y += 1; d.z += 1; d.w += 1;   // self-loops
    } else {
        if (i0 + 0 < N) { d.x = g_deg[i0 + 0] + 1; g_deg[i0 + 0] = 0; }
        if (i0 + 1 < N) { d.y = g_deg[i0 + 1] + 1; g_deg[i0 + 1] = 0; }
        if (i0 + 2 < N) { d.z = g_deg[i0 + 2] + 1; g_deg[i0 + 2] = 0; }
        if (i0 + 3 < N) { d.w = g_deg[i0 + 3] + 1; g_deg[i0 + 3] = 0; }
    }
    int T = d.x + d.y + d.z + d.w;
    int v = T;
    #pragma unroll
    for (int o = 1; o < 32; o <<= 1) {
        int t = __shfl_up_sync(0xffffffffu, v, o);
        if (lane >= o) v += t;
    }
    if (lane == 31) wsum[warp] = v;
    __syncthreads();
    if (warp == 0) {
        int w = (lane < 8) ? wsum[lane] : 0;
        #pragma unroll
        for (int o = 1; o < 8; o <<= 1) {
            int t = __shfl_up_sync(0xffffffffu, w, o);
            if (lane >= o) w += t;
        }
        if (lane < 8) wsum[lane] = w;
        if (lane == 0) {
            g_agg[b] = wsum[7];
            __threadfence();
            atomicExch(&g_flag[b], 1);
        }
    }
    __syncthreads();
    int blk_scan = (warp ? wsum[warp - 1] : 0);

    if (warp == 0) {
        int base = 0;
        for (int i = lane; i < b; i += 32) {
            while (atomicAdd(&g_flag[i], 0) == 0) {}
            base += g_agg[i];
        }
        #pragma unroll
        for (int o = 16; o > 0; o >>= 1) base += __shfl_xor_sync(0xffffffffu, base, o);
        if (lane == 0) s_base = base;
    }
    __syncthreads();

    int excl = v - T + blk_scan + s_base;
    int p = excl;
    if (i0 + 0 < N) { g_cursor[i0 + 0] = p; g_off[i0 + 1] = p + d.x; p += d.x; }
    if (i0 + 1 < N) { g_cursor[i0 + 1] = p; g_off[i0 + 2] = p + d.y; p += d.y; }
    if (i0 + 2 < N) { g_cursor[i0 + 2] = p; g_off[i0 + 3] = p + d.z; p += d.z; }
    if (i0 + 3 < N) { g_cursor[i0 + 3] = p; g_off[i0 + 4] = p + d.w; }
    if (b == 0 && tid == 0) g_off[0] = 0;
}

// ------------------- MMA / ldmatrix helpers -------------------
__device__ __forceinline__ void mma_bf16(float c[4], const uint32_t a[4],
                                         uint32_t b0, uint32_t b1) {
    asm volatile(
        "mma.sync.aligned.m16n8k16.row.col.f32.bf16.bf16.f32 "
        "{%0,%1,%2,%3}, {%4,%5,%6,%7}, {%8,%9}, {%0,%1,%2,%3};"
        : "+f"(c[0]), "+f"(c[1]), "+f"(c[2]), "+f"(c[3])
        : "r"(a[0]), "r"(a[1]), "r"(a[2]), "r"(a[3]), "r"(b0), "r"(b1));
}
__device__ __forceinline__ void ldsm_x4(uint32_t d[4], uint32_t addr) {
    asm volatile("ldmatrix.sync.aligned.m8n8.x4.shared.b16 {%0,%1,%2,%3}, [%4];"
                 : "=r"(d[0]), "=r"(d[1]), "=r"(d[2]), "=r"(d[3]) : "r"(addr));
}
__device__ __forceinline__ uint32_t s2u(const void* p) {
    return (uint32_t)__cvta_generic_to_shared(p);
}

// ------------------- fused HMMA GEMM (h + skip) + att logits [+ scatter side-blocks] --
// Blocks [0, gemm_nb): GEMM tile M=64 x N=256 (round-11 structure).
// Blocks >= gemm_nb: CSR scatter (needs scan done; independent of GEMM role).
__global__ void __launch_bounds__(256, 2)
gat_mma_fused(const float* __restrict__ X,
              const uint32_t* __restrict__ Bhi, const uint32_t* __restrict__ Blo,
              const float* __restrict__ a_src, const float* __restrict__ a_dst,
              int nrows, int gemm_nb,
              const int* __restrict__ srcE, const int* __restrict__ dstE, int E) {
    int tid = threadIdx.x;

    if ((int)blockIdx.x >= gemm_nb) {   // ---- scatter role ----
        int nbs = gridDim.x - gemm_nb;
        int base = (blockIdx.x - gemm_nb) * 256 + tid;
        if (base < MAX_NB) g_flag[base] = 0;   // reset lookback flags for next replay
        for (int i = base; i < E + nrows; i += nbs * 256) {
            int s, dn;
            if (i < E) { s = srcE[i]; dn = dstE[i]; }
            else       { s = dn = i - E; }
            int p = atomicAdd(&g_cursor[dn], 1);
            g_csr[p] = s;
        }
        return;
    }

    extern __shared__ uint32_t dsm[];
    __shared__ float s_att[256];
    uint32_t* Ah = dsm;            // 64*68
    uint32_t* Al = dsm + 4352;
    uint32_t* Bh = dsm + 8704;     // 256*36
    uint32_t* Bl = dsm + 17920;

    int row0 = blockIdx.x * 64;
    if (tid < 128) { s_att[tid] = a_src[tid]; s_att[128 + tid] = a_dst[tid]; }

    #pragma unroll
    for (int it = 0; it < 16; it++) {
        int idx = tid + it * 256;
        int r = idx >> 6;
        int w = idx & 63;
        float x0 = 0.f, x1 = 0.f;
        int gr = row0 + r;
        if (gr < nrows) {
            float2 v = *(const float2*)(X + (size_t)gr * 128 + w * 2);
            x0 = v.x; x1 = v.y;
        }
        __nv_bfloat16 h0 = __float2bfloat16(x0);
        __nv_bfloat16 h1 = __float2bfloat16(x1);
        __nv_bfloat16 l0 = __float2bfloat16(x0 - __bfloat162float(h0));
        __nv_bfloat16 l1 = __float2bfloat16(x1 - __bfloat162float(h1));
        Ah[r * 68 + w] = ((uint32_t)__bfloat16_as_ushort(h1) << 16) | __bfloat16_as_ushort(h0);
        Al[r * 68 + w] = ((uint32_t)__bfloat16_as_ushort(l1) << 16) | __bfloat16_as_ushort(l0);
    }

    int lane = tid & 31, warp = tid >> 5;
    int mi = warp & 1, ni = warp >> 1;
    int g = lane >> 2, t = lane & 3;
    int mloc  = mi * 32;
    int nbase = ni * 64;

    uint32_t a_off = (uint32_t)(((mloc + (lane & 15)) * 68 + ((lane >> 4) << 2)) * 4);
    uint32_t ah_base = s2u(Ah) + a_off;
    uint32_t al_base = s2u(Al) + a_off;
    uint32_t b_off = (uint32_t)((((nbase + ((lane >> 4) << 3) + (lane & 7)) * 36)
                                 + (((lane >> 3) & 1) << 2)) * 4);
    uint32_t bh_base = s2u(Bh) + b_off;
    uint32_t bl_base = s2u(Bl) + b_off;

    float acc[2][8][4];
    #pragma unroll
    for (int a = 0; a < 2; a++)
        #pragma unroll
        for (int b = 0; b < 8; b++)
            #pragma unroll
            for (int c = 0; c < 4; c++) acc[a][b][c] = 0.f;

    for (int kc = 0; kc < 2; kc++) {
        if (kc) __syncthreads();
        #pragma unroll
        for (int it = 0; it < 32; it++) {
            int idx = tid + it * 256;
            int r = idx >> 5;
            int w = idx & 31;
            Bh[r * 36 + w] = Bhi[r * 64 + kc * 32 + w];
            Bl[r * 36 + w] = Blo[r * 64 + kc * 32 + w];
        }
        __syncthreads();

        #pragma unroll
        for (int ksl = 0; ksl < 4; ksl++) {
            uint32_t kb = (uint32_t)((kc * 32 + ksl * 8) * 4);
            uint32_t bb = (uint32_t)((ksl * 8) * 4);
            uint32_t ah[2][4], al[2][4], bf[4][4];
            ldsm_x4(ah[0], ah_base + kb);
            ldsm_x4(ah[1], ah_base + kb + 16 * 68 * 4);
            ldsm_x4(al[0], al_base + kb);
            ldsm_x4(al[1], al_base + kb + 16 * 68 * 4);
            #pragma unroll
            for (int q = 0; q < 4; q++)
                ldsm_x4(bf[q], bh_base + bb + (uint32_t)(q * 16 * 36 * 4));
            #pragma unroll
            for (int q = 0; q < 4; q++) {
                mma_bf16(acc[0][2 * q],     ah[0], bf[q][0], bf[q][1]);
                mma_bf16(acc[1][2 * q],     ah[1], bf[q][0], bf[q][1]);
                mma_bf16(acc[0][2 * q + 1], ah[0], bf[q][2], bf[q][3]);
                mma_bf16(acc[1][2 * q + 1], ah[1], bf[q][2], bf[q][3]);
            }
            #pragma unroll
            for (int q = 0; q < 4; q++) {
                mma_bf16(acc[0][2 * q],     al[0], bf[q][0], bf[q][1]);
                mma_bf16(acc[1][2 * q],     al[1], bf[q][0], bf[q][1]);
                mma_bf16(acc[0][2 * q + 1], al[0], bf[q][2], bf[q][3]);
                mma_bf16(acc[1][2 * q + 1], al[1], bf[q][2], bf[q][3]);
            }
            #pragma unroll
            for (int q = 0; q < 4; q++)
                ldsm_x4(bf[q], bl_base + bb + (uint32_t)(q * 16 * 36 * 4));
            #pragma unroll
            for (int q = 0; q < 4; q++) {
                mma_bf16(acc[0][2 * q],     ah[0], bf[q][0], bf[q][1]);
                mma_bf16(acc[1][2 * q],     ah[1], bf[q][0], bf[q][1]);
                mma_bf16(acc[0][2 * q + 1], ah[0], bf[q][2], bf[q][3]);
                mma_bf16(acc[1][2 * q + 1], ah[1], bf[q][2], bf[q][3]);
            }
        }
    }

    int gr0 = row0 + mloc;
    if (ni < 2) {
        float ps[2][2][2], pd[2][2][2];
        #pragma unroll
        for (int a = 0; a < 2; a++)
            #pragma unroll
            for (int b = 0; b < 2; b++) {
                ps[a][b][0] = ps[a][b][1] = 0.f;
                pd[a][b][0] = pd[a][b][1] = 0.f;
            }
        #pragma unroll
        for (int mt = 0; mt < 2; mt++) {
            int r0 = gr0 + mt * 16 + g;
            int r1 = r0 + 8;
            #pragma unroll
            for (int nt = 0; nt < 8; nt++) {
                int col = nbase + nt * 8 + t * 2;
                int hh = nt >> 2;
                float s0 = s_att[col],       s1 = s_att[col + 1];
                float d0 = s_att[128 + col], d1 = s_att[128 + col + 1];
                ps[mt][0][hh] += acc[mt][nt][0] * s0 + acc[mt][nt][1] * s1;
                pd[mt][0][hh] += acc[mt][nt][0] * d0 + acc[mt][nt][1] * d1;
                ps[mt][1][hh] += acc[mt][nt][2] * s0 + acc[mt][nt][3] * s1;
                pd[mt][1][hh] += acc[mt][nt][2] * d0 + acc[mt][nt][3] * d1;
                if (r0 < nrows)
                    g_hh[(size_t)r0 * 64 + (col >> 1)] =
                        __floats2half2_rn(acc[mt][nt][0], acc[mt][nt][1]);
                if (r1 < nrows)
                    g_hh[(size_t)r1 * 64 + (col >> 1)] =
                        __floats2half2_rn(acc[mt][nt][2], acc[mt][nt][3]);
            }
        }
        #pragma unroll
        for (int mt = 0; mt < 2; mt++)
            #pragma unroll
            for (int rs = 0; rs < 2; rs++)
                #pragma unroll
                for (int hh = 0; hh < 2; hh++) {
                    float vs = ps[mt][rs][hh];
                    float vd = pd[mt][rs][hh];
                    vs += __shfl_xor_sync(0xffffffffu, vs, 1);
                    vs += __shfl_xor_sync(0xffffffffu, vs, 2);
                    vd += __shfl_xor_sync(0xffffffffu, vd, 1);
                    vd += __shfl_xor_sync(0xffffffffu, vd, 2);
                    if (t == 0) {
                        int r = gr0 + mt * 16 + g + rs * 8;
                        if (r < nrows) {
                            int head = ni * 2 + hh;
                            g_asrc[r * 4 + head] = vs;
                            g_adst[r * 4 + head] = vd;
                        }
                    }
                }
    } else {
        int cb = nbase - 128;
        #pragma unroll
        for (int mt = 0; mt < 2; mt++) {
            int r0 = gr0 + mt * 16 + g;
            int r1 = r0 + 8;
            #pragma unroll
            for (int nt = 0; nt < 8; nt++) {
                int col = cb + nt * 8 + t * 2;
                if (r0 < nrows)
                    *(float2*)(g_skip + (size_t)r0 * 128 + col) =
                        make_float2(acc[mt][nt][0], acc[mt][nt][1]);
                if (r1 < nrows)
                    *(float2*)(g_skip + (size_t)r1 * 128 + col) =
                        make_float2(acc[mt][nt][2], acc[mt][nt][3]);
            }
        }
    }
}

// ------------------- online-softmax aggregate (fp16 gather, 4-edge batched) ----------
__global__ void __launch_bounds__(256)
agg_kernel(const float* __restrict__ bias, float* __restrict__ out, int N) {
    int gw = (blockIdx.x * blockDim.x + threadIdx.x) >> 5;
    int lane = threadIdx.x & 31;
    if (gw >= N) return;
    int n = gw;
    int beg = g_off[n];
    int end = g_off[n + 1];
    int head = lane >> 3;

    float adh = g_adst[n * 4 + head];
    const uint2* H = (const uint2*)g_hh;    // row stride 32 uint2 (= 128 halves)

    float m = -INFINITY;
    float denom = 0.0f;
    float4 acc = make_float4(0.f, 0.f, 0.f, 0.f);

    int j = beg;
    for (; j + 4 <= end; j += 4) {
        int s0 = g_csr[j];
        int s1 = g_csr[j + 1];
        int s2 = g_csr[j + 2];
        int s3 = g_csr[j + 3];
        float a0 = g_asrc[s0 * 4 + head];
        float a1 = g_asrc[s1 * 4 + head];
        float a2 = g_asrc[s2 * 4 + head];
        float a3 = g_asrc[s3 * 4 + head];
        uint2 u0 = H[(size_t)s0 * 32 + lane];
        uint2 u1 = H[(size_t)s1 * 32 + lane];
        uint2 u2 = H[(size_t)s2 * 32 + lane];
        uint2 u3 = H[(size_t)s3 * 32 + lane];

        float e0 = a0 + adh; e0 = (e0 > 0.f) ? e0 : NEG_SLOPE * e0;
        float e1 = a1 + adh; e1 = (e1 > 0.f) ? e1 : NEG_SLOPE * e1;
        float e2 = a2 + adh; e2 = (e2 > 0.f) ? e2 : NEG_SLOPE * e2;
        float e3 = a3 + adh; e3 = (e3 > 0.f) ? e3 : NEG_SLOPE * e3;

        float mx = fmaxf(fmaxf(e0, e1), fmaxf(e2, e3));
        if (mx > m) {
            float sc = __expf(m - mx);
            denom *= sc;
            acc.x *= sc; acc.y *= sc; acc.z *= sc; acc.w *= sc;
            m = mx;
        }
        float w0 = __expf(e0 - m);
        float w1 = __expf(e1 - m);
        float w2 = __expf(e2 - m);
        float w3 = __expf(e3 - m);
        denom += (w0 + w1) + (w2 + w3);
        float2 f0a = __half22float2(*(__half2*)&u0.x), f0b = __half22float2(*(__half2*)&u0.y);
        float2 f1a = __half22float2(*(__half2*)&u1.x), f1b = __half22float2(*(__half2*)&u1.y);
        float2 f2a = __half22float2(*(__half2*)&u2.x), f2b = __half22float2(*(__half2*)&u2.y);
        float2 f3a = __half22float2(*(__half2*)&u3.x), f3b = __half22float2(*(__half2*)&u3.y);
        acc.x += w0 * f0a.x + w1 * f1a.x + w2 * f2a.x + w3 * f3a.x;
        acc.y += w0 * f0a.y + w1 * f1a.y + w2 * f2a.y + w3 * f3a.y;
        acc.z += w0 * f0b.x + w1 * f1b.x + w2 * f2b.x + w3 * f3b.x;
        acc.w += w0 * f0b.y + w1 * f1b.y + w2 * f2b.y + w3 * f3b.y;
    }
    for (; j < end; j++) {
        int s = g_csr[j];
        float a = g_asrc[s * 4 + head];
        float e = a + adh; e = (e > 0.f) ? e : NEG_SLOPE * e;
        uint2 u = H[(size_t)s * 32 + lane];
        if (e > m) {
            float sc = __expf(m - e);
            denom *= sc;
            acc.x *= sc; acc.y *= sc; acc.z *= sc; acc.w *= sc;
            m = e;
        }
        float w = __expf(e - m);
        denom += w;
        float2 fa = __half22float2(*(__half2*)&u.x);
        float2 fb = __half22float2(*(__half2*)&u.y);
        acc.x += w * fa.x; acc.y += w * fa.y; acc.z += w * fb.x; acc.w += w * fb.y;
    }

    float inv = 1.0f / (denom + 1e-16f);
    float4 b  = ((const float4*)bias)[lane];
    float4 sk = ((const float4*)g_skip)[(size_t)n * 32 + lane];
    float4 o;
    o.x = acc.x * inv + b.x + sk.x;
    o.y = acc.y * inv + b.y + sk.y;
    o.z = acc.z * inv + b.z + sk.z;
    o.w = acc.w * inv + b.w + sk.w;
    o.x = (o.x > 0.f) ? o.x : expm1f(o.x);
    o.y = (o.y > 0.f) ? o.y : expm1f(o.y);
    o.z = (o.z > 0.f) ? o.z : expm1f(o.z);
    o.w = (o.w > 0.f) ? o.w : expm1f(o.w);
    ((float4*)out)[(size_t)n * 32 + lane] = o;
}

// ------------------- launch -------------------
extern "C" void kernel_launch(void* const* d_in, const int* in_sizes, int n_in,
                              void* d_out, int out_size) {
    const float* x    = (const float*)d_in[0];
    const int*   ei   = (const int*)  d_in[1];
    const float* W1   = (const float*)d_in[2];
    const float* as1  = (const float*)d_in[3];
    const float* ad1  = (const float*)d_in[4];
    const float* b1   = (const float*)d_in[5];
    const float* Ws1  = (const float*)d_in[6];
    const float* W2   = (const float*)d_in[7];
    const float* as2  = (const float*)d_in[8];
    const float* ad2  = (const float*)d_in[9];
    const float* b2   = (const float*)d_in[10];
    const float* Ws2  = (const float*)d_in[11];

    int N = in_sizes[0] / DIM;
    int E = in_sizes[1] / 2;
    const int* src = ei;
    const int* dst = ei + E;

    float* buf1;  cudaGetSymbolAddress((void**)&buf1, g_buf1);
    __nv_bfloat16* bhi; cudaGetSymbolAddress((void**)&bhi, g_bhi);
    __nv_bfloat16* blo; cudaGetSymbolAddress((void**)&blo, g_blo);

    const size_t dyn = 27136 * 4;
    cudaFuncSetAttribute(gat_mma_fused, cudaFuncAttributeMaxDynamicSharedMemorySize, (int)dyn);

    int nb = (N + SCAN_CHUNK - 1) / SCAN_CHUNK;
    int gemm_blocks = (N + 63) / 64;
    int warp_blocks = (N * 32 + 255) / 256;

    // launch idx:
    prep_hist<<<WPREP_BLKS + 1024, 256>>>(W1, Ws1, W2, Ws2, dst, E);         // 0
    scan_lookback<<<nb, 256>>>(N);                                           // 1
    gat_mma_fused<<<gemm_blocks + SCAT_BLKS, 256, dyn>>>(                    // 2 (gemm1+scatter)
        x, (const uint32_t*)bhi, (const uint32_t*)blo, as1, ad1, N,
        gemm_blocks, src, dst, E);
    agg_kernel<<<warp_blocks, 256>>>(b1, buf1, N);                           // 3 <- profiled
    gat_mma_fused<<<gemm_blocks, 256, dyn>>>(                                // 4 (gemm2, no scatter)
        buf1, (const uint32_t*)(bhi + 256 * 128), (const uint32_t*)(blo + 256 * 128),
        as2, ad2, N, gemm_blocks, nullptr, nullptr, 0);
    agg_kernel<<<warp_blocks, 256>>>(b2, (float*)d_out, N);                  // 5
}

// round 13
// speedup vs baseline: 1.2214x; 1.0401x over previous
#include <cuda_runtime.h>
#include <cuda_bf16.h>
#include <stdint.h>
#include <math.h>

#define DIM 128
#define HEADS 4
#define NEG_SLOPE 0.2f
#define MAX_N 50000
#define MAX_E 600000
#define SCAN_CHUNK 1024
#define MAX_NB ((MAX_N + SCAN_CHUNK - 1) / SCAN_CHUNK)
#define WPREP_BLKS 256   // 65536 weight elems / 256 thr
#define SCAT_BLKS 1024   // scatter-role blocks appended to GEMM-1

// ------------------- scratch (static device globals; no allocs) -------------------
__device__ float g_h[MAX_N * DIM];
__device__ float g_skip[MAX_N * DIM];
__device__ float g_buf1[MAX_N * DIM];
__device__ float g_asrc[MAX_N * HEADS];
__device__ float g_adst[MAX_N * HEADS];
__device__ int   g_deg[MAX_N];           // zero-invariant: scan re-zeroes after read
__device__ int   g_off[MAX_N + 1];
__device__ int   g_cursor[MAX_N];
__device__ int   g_csr[MAX_E + MAX_N];
__device__ int   g_agg[MAX_NB];
__device__ int   g_flag[MAX_NB];         // zero-invariant: scatter role re-zeroes
// combined transposed weights per layer: Bt[n][k]: n<128 -> W[k][n], else Wskip[k][n-128]
__device__ __nv_bfloat16 g_bhi[2 * 256 * 128];
__device__ __nv_bfloat16 g_blo[2 * 256 * 128];

// ------------------- prep (weights) + degree histogram, role-split -------------------
__global__ void prep_hist(const float* __restrict__ W1, const float* __restrict__ Ws1,
                          const float* __restrict__ W2, const float* __restrict__ Ws2,
                          const int* __restrict__ dst, int E) {
    int tid = threadIdx.x;
    if ((int)blockIdx.x < WPREP_BLKS) {
        int idx = blockIdx.x * 256 + tid;                 // 0..65535
        int layer = idx >> 15;
        int rem   = idx & 32767;
        int n     = rem >> 7;
        int k     = rem & 127;
        const float* W = layer ? (n < 128 ? W2 : Ws2) : (n < 128 ? W1 : Ws1);
        float v = W[k * 128 + (n & 127)];
        __nv_bfloat16 hi = __float2bfloat16(v);
        float lo = v - __bfloat162float(hi);
        g_bhi[idx] = hi;
        g_blo[idx] = __float2bfloat16(lo);
    } else {
        int nbh = gridDim.x - WPREP_BLKS;
        for (int i = (blockIdx.x - WPREP_BLKS) * 256 + tid; i < E; i += nbh * 256)
            atomicAdd(&g_deg[dst[i]], 1);
    }
}

// ------------------- single-kernel scan with decoupled lookback -------------------
__global__ void scan_lookback(int N) {
    __shared__ int wsum[8];
    __shared__ int s_base;
    int tid = threadIdx.x;
    int lane = tid & 31, warp = tid >> 5;
    int b = blockIdx.x;
    int i0 = b * SCAN_CHUNK + tid * 4;

    int4 d = make_int4(0, 0, 0, 0);
    if (i0 + 3 < N) {
        d = *(const int4*)(g_deg + i0);
        *(int4*)(g_deg + i0) = make_int4(0, 0, 0, 0);
        d.x += 1; d.y += 1; d.z += 1; d.w += 1;   // self-loops
    } else {
        if (i0 + 0 < N) { d.x = g_deg[i0 + 0] + 1; g_deg[i0 + 0] = 0; }
        if (i0 + 1 < N) { d.y = g_deg[i0 + 1] + 1; g_deg[i0 + 1] = 0; }
        if (i0 + 2 < N) { d.z = g_deg[i0 + 2] + 1; g_deg[i0 + 2] = 0; }
        if (i0 + 3 < N) { d.w = g_deg[i0 + 3] + 1; g_deg[i0 + 3] = 0; }
    }
    int T = d.x + d.y + d.z + d.w;
    int v = T;
    #pragma unroll
    for (int o = 1; o < 32; o <<= 1) {
        int t = __shfl_up_sync(0xffffffffu, v, o);
        if (lane >= o) v += t;
    }
    if (lane == 31) wsum[warp] = v;
    __syncthreads();
    if (warp == 0) {
        int w = (lane < 8) ? wsum[lane] : 0;
        #pragma unroll
        for (int o = 1; o < 8; o <<= 1) {
            int t = __shfl_up_sync(0xffffffffu, w, o);
            if (lane >= o) w += t;
        }
        if (lane < 8) wsum[lane] = w;
        if (lane == 0) {
            g_agg[b] = wsum[7];
            __threadfence();
            atomicExch(&g_flag[b], 1);
        }
    }
    __syncthreads();
    int blk_scan = (warp ? wsum[warp - 1] : 0);

    if (warp == 0) {
        int base = 0;
        for (int i = lane; i < b; i += 32) {
            while (atomicAdd(&g_flag[i], 0) == 0) {}
            base += g_agg[i];
        }
        #pragma unroll
        for (int o = 16; o > 0; o >>= 1) base += __shfl_xor_sync(0xffffffffu, base, o);
        if (lane == 0) s_base = base;
    }
    __syncthreads();

    int excl = v - T + blk_scan + s_base;
    int p = excl;
    if (i0 + 0 < N) { g_cursor[i0 + 0] = p; g_off[i0 + 1] = p + d.x; p += d.x; }
    if (i0 + 1 < N) { g_cursor[i0 + 1] = p; g_off[i0 + 2] = p + d.y; p += d.y; }
    if (i0 + 2 < N) { g_cursor[i0 + 2] = p; g_off[i0 + 3] = p + d.z; p += d.z; }
    if (i0 + 3 < N) { g_cursor[i0 + 3] = p; g_off[i0 + 4] = p + d.w; }
    if (b == 0 && tid == 0) g_off[0] = 0;
}

// ------------------- MMA / ldmatrix helpers -------------------
__device__ __forceinline__ void mma_bf16(float c[4], const uint32_t a[4],
                                         uint32_t b0, uint32_t b1) {
    asm volatile(
        "mma.sync.aligned.m16n8k16.row.col.f32.bf16.bf16.f32 "
        "{%0,%1,%2,%3}, {%4,%5,%6,%7}, {%8,%9}, {%0,%1,%2,%3};"
        : "+f"(c[0]), "+f"(c[1]), "+f"(c[2]), "+f"(c[3])
        : "r"(a[0]), "r"(a[1]), "r"(a[2]), "r"(a[3]), "r"(b0), "r"(b1));
}
__device__ __forceinline__ void ldsm_x4(uint32_t d[4], uint32_t addr) {
    asm volatile("ldmatrix.sync.aligned.m8n8.x4.shared.b16 {%0,%1,%2,%3}, [%4];"
                 : "=r"(d[0]), "=r"(d[1]), "=r"(d[2]), "=r"(d[3]) : "r"(addr));
}
__device__ __forceinline__ uint32_t s2u(const void* p) {
    return (uint32_t)__cvta_generic_to_shared(p);
}

// ------------------- fused HMMA GEMM (h + skip) + att logits [+ scatter side-blocks] --
__global__ void __launch_bounds__(256, 2)
gat_mma_fused(const float* __restrict__ X,
              const uint32_t* __restrict__ Bhi, const uint32_t* __restrict__ Blo,
              const float* __restrict__ a_src, const float* __restrict__ a_dst,
              int nrows, int gemm_nb,
              const int* __restrict__ srcE, const int* __restrict__ dstE, int E) {
    int tid = threadIdx.x;

    if ((int)blockIdx.x >= gemm_nb) {   // ---- scatter role ----
        int nbs = gridDim.x - gemm_nb;
        int base = (blockIdx.x - gemm_nb) * 256 + tid;
        if (base < MAX_NB) g_flag[base] = 0;   // reset lookback flags for next replay
        for (int i = base; i < E + nrows; i += nbs * 256) {
            int s, dn;
            if (i < E) { s = srcE[i]; dn = dstE[i]; }
            else       { s = dn = i - E; }
            int p = atomicAdd(&g_cursor[dn], 1);
            g_csr[p] = s;
        }
        return;
    }

    extern __shared__ uint32_t dsm[];
    __shared__ float s_att[256];
    uint32_t* Ah = dsm;            // 64*68
    uint32_t* Al = dsm + 4352;
    uint32_t* Bh = dsm + 8704;     // 256*36
    uint32_t* Bl = dsm + 17920;

    int row0 = blockIdx.x * 64;
    if (tid < 128) { s_att[tid] = a_src[tid]; s_att[128 + tid] = a_dst[tid]; }

    #pragma unroll
    for (int it = 0; it < 16; it++) {
        int idx = tid + it * 256;
        int r = idx >> 6;
        int w = idx & 63;
        float x0 = 0.f, x1 = 0.f;
        int gr = row0 + r;
        if (gr < nrows) {
            float2 v = *(const float2*)(X + (size_t)gr * 128 + w * 2);
            x0 = v.x; x1 = v.y;
        }
        __nv_bfloat16 h0 = __float2bfloat16(x0);
        __nv_bfloat16 h1 = __float2bfloat16(x1);
        __nv_bfloat16 l0 = __float2bfloat16(x0 - __bfloat162float(h0));
        __nv_bfloat16 l1 = __float2bfloat16(x1 - __bfloat162float(h1));
        Ah[r * 68 + w] = ((uint32_t)__bfloat16_as_ushort(h1) << 16) | __bfloat16_as_ushort(h0);
        Al[r * 68 + w] = ((uint32_t)__bfloat16_as_ushort(l1) << 16) | __bfloat16_as_ushort(l0);
    }

    int lane = tid & 31, warp = tid >> 5;
    int mi = warp & 1, ni = warp >> 1;
    int g = lane >> 2, t = lane & 3;
    int mloc  = mi * 32;
    int nbase = ni * 64;

    uint32_t a_off = (uint32_t)(((mloc + (lane & 15)) * 68 + ((lane >> 4) << 2)) * 4);
    uint32_t ah_base = s2u(Ah) + a_off;
    uint32_t al_base = s2u(Al) + a_off;
    uint32_t b_off = (uint32_t)((((nbase + ((lane >> 4) << 3) + (lane & 7)) * 36)
                                 + (((lane >> 3) & 1) << 2)) * 4);
    uint32_t bh_base = s2u(Bh) + b_off;
    uint32_t bl_base = s2u(Bl) + b_off;

    float acc[2][8][4];
    #pragma unroll
    for (int a = 0; a < 2; a++)
        #pragma unroll
        for (int b = 0; b < 8; b++)
            #pragma unroll
            for (int c = 0; c < 4; c++) acc[a][b][c] = 0.f;

    for (int kc = 0; kc < 2; kc++) {
        if (kc) __syncthreads();
        #pragma unroll
        for (int it = 0; it < 32; it++) {
            int idx = tid + it * 256;
            int r = idx >> 5;
            int w = idx & 31;
            Bh[r * 36 + w] = Bhi[r * 64 + kc * 32 + w];
            Bl[r * 36 + w] = Blo[r * 64 + kc * 32 + w];
        }
        __syncthreads();

        #pragma unroll
        for (int ksl = 0; ksl < 4; ksl++) {
            uint32_t kb = (uint32_t)((kc * 32 + ksl * 8) * 4);
            uint32_t bb = (uint32_t)((ksl * 8) * 4);
            uint32_t ah[2][4], al[2][4], bf[4][4];
            ldsm_x4(ah[0], ah_base + kb);
            ldsm_x4(ah[1], ah_base + kb + 16 * 68 * 4);
            ldsm_x4(al[0], al_base + kb);
            ldsm_x4(al[1], al_base + kb + 16 * 68 * 4);
            #pragma unroll
            for (int q = 0; q < 4; q++)
                ldsm_x4(bf[q], bh_base + bb + (uint32_t)(q * 16 * 36 * 4));
            #pragma unroll
            for (int q = 0; q < 4; q++) {
                mma_bf16(acc[0][2 * q],     ah[0], bf[q][0], bf[q][1]);
                mma_bf16(acc[1][2 * q],     ah[1], bf[q][0], bf[q][1]);
                mma_bf16(acc[0][2 * q + 1], ah[0], bf[q][2], bf[q][3]);
                mma_bf16(acc[1][2 * q + 1], ah[1], bf[q][2], bf[q][3]);
            }
            #pragma unroll
            for (int q = 0; q < 4; q++) {
                mma_bf16(acc[0][2 * q],     al[0], bf[q][0], bf[q][1]);
                mma_bf16(acc[1][2 * q],     al[1], bf[q][0], bf[q][1]);
                mma_bf16(acc[0][2 * q + 1], al[0], bf[q][2], bf[q][3]);
                mma_bf16(acc[1][2 * q + 1], al[1], bf[q][2], bf[q][3]);
            }
            #pragma unroll
            for (int q = 0; q < 4; q++)
                ldsm_x4(bf[q], bl_base + bb + (uint32_t)(q * 16 * 36 * 4));
            #pragma unroll
            for (int q = 0; q < 4; q++) {
                mma_bf16(acc[0][2 * q],     ah[0], bf[q][0], bf[q][1]);
                mma_bf16(acc[1][2 * q],     ah[1], bf[q][0], bf[q][1]);
                mma_bf16(acc[0][2 * q + 1], ah[0], bf[q][2], bf[q][3]);
                mma_bf16(acc[1][2 * q + 1], ah[1], bf[q][2], bf[q][3]);
            }
        }
    }

    int gr0 = row0 + mloc;
    if (ni < 2) {
        float ps[2][2][2], pd[2][2][2];
        #pragma unroll
        for (int a = 0; a < 2; a++)
            #pragma unroll
            for (int b = 0; b < 2; b++) {
                ps[a][b][0] = ps[a][b][1] = 0.f;
                pd[a][b][0] = pd[a][b][1] = 0.f;
            }
        #pragma unroll
        for (int mt = 0; mt < 2; mt++) {
            int r0 = gr0 + mt * 16 + g;
            int r1 = r0 + 8;
            #pragma unroll
            for (int nt = 0; nt < 8; nt++) {
                int col = nbase + nt * 8 + t * 2;
                int hh = nt >> 2;
                float s0 = s_att[col],       s1 = s_att[col + 1];
                float d0 = s_att[128 + col], d1 = s_att[128 + col + 1];
                ps[mt][0][hh] += acc[mt][nt][0] * s0 + acc[mt][nt][1] * s1;
                pd[mt][0][hh] += acc[mt][nt][0] * d0 + acc[mt][nt][1] * d1;
                ps[mt][1][hh] += acc[mt][nt][2] * s0 + acc[mt][nt][3] * s1;
                pd[mt][1][hh] += acc[mt][nt][2] * d0 + acc[mt][nt][3] * d1;
                if (r0 < nrows)
                    *(float2*)(g_h + (size_t)r0 * 128 + col) =
                        make_float2(acc[mt][nt][0], acc[mt][nt][1]);
                if (r1 < nrows)
                    *(float2*)(g_h + (size_t)r1 * 128 + col) =
                        make_float2(acc[mt][nt][2], acc[mt][nt][3]);
            }
        }
        #pragma unroll
        for (int mt = 0; mt < 2; mt++)
            #pragma unroll
            for (int rs = 0; rs < 2; rs++)
                #pragma unroll
                for (int hh = 0; hh < 2; hh++) {
                    float vs = ps[mt][rs][hh];
                    float vd = pd[mt][rs][hh];
                    vs += __shfl_xor_sync(0xffffffffu, vs, 1);
                    vs += __shfl_xor_sync(0xffffffffu, vs, 2);
                    vd += __shfl_xor_sync(0xffffffffu, vd, 1);
                    vd += __shfl_xor_sync(0xffffffffu, vd, 2);
                    if (t == 0) {
                        int r = gr0 + mt * 16 + g + rs * 8;
                        if (r < nrows) {
                            int head = ni * 2 + hh;
                            g_asrc[r * 4 + head] = vs;
                            g_adst[r * 4 + head] = vd;
                        }
                    }
                }
    } else {
        int cb = nbase - 128;
        #pragma unroll
        for (int mt = 0; mt < 2; mt++) {
            int r0 = gr0 + mt * 16 + g;
            int r1 = r0 + 8;
            #pragma unroll
            for (int nt = 0; nt < 8; nt++) {
                int col = cb + nt * 8 + t * 2;
                if (r0 < nrows)
                    *(float2*)(g_skip + (size_t)r0 * 128 + col) =
                        make_float2(acc[mt][nt][0], acc[mt][nt][1]);
                if (r1 < nrows)
                    *(float2*)(g_skip + (size_t)r1 * 128 + col) =
                        make_float2(acc[mt][nt][2], acc[mt][nt][3]);
            }
        }
    }
}

// ------------------- softmax aggregate: no-max exp (bounded logits), 4-edge batched ---
__global__ void __launch_bounds__(256)
agg_kernel(const float* __restrict__ bias, float* __restrict__ out, int N) {
    int gw = (blockIdx.x * blockDim.x + threadIdx.x) >> 5;
    int lane = threadIdx.x & 31;
    if (gw >= N) return;
    int n = gw;
    int beg = g_off[n];
    int end = g_off[n + 1];
    int head = lane >> 3;

    float adh = g_adst[n * 4 + head];
    const float4* h4 = (const float4*)g_h;

    float denom = 0.0f;
    float4 acc = make_float4(0.f, 0.f, 0.f, 0.f);

    int j = beg;
    for (; j + 4 <= end; j += 4) {
        int s0 = g_csr[j];
        int s1 = g_csr[j + 1];
        int s2 = g_csr[j + 2];
        int s3 = g_csr[j + 3];
        float a0 = g_asrc[s0 * 4 + head];
        float a1 = g_asrc[s1 * 4 + head];
        float a2 = g_asrc[s2 * 4 + head];
        float a3 = g_asrc[s3 * 4 + head];
        float4 v0 = h4[s0 * 32 + lane];
        float4 v1 = h4[s1 * 32 + lane];
        float4 v2 = h4[s2 * 32 + lane];
        float4 v3 = h4[s3 * 32 + lane];

        float e0 = a0 + adh; e0 = (e0 > 0.f) ? e0 : NEG_SLOPE * e0;
        float e1 = a1 + adh; e1 = (e1 > 0.f) ? e1 : NEG_SLOPE * e1;
        float e2 = a2 + adh; e2 = (e2 > 0.f) ? e2 : NEG_SLOPE * e2;
        float e3 = a3 + adh; e3 = (e3 > 0.f) ? e3 : NEG_SLOPE * e3;

        float w0 = __expf(e0);
        float w1 = __expf(e1);
        float w2 = __expf(e2);
        float w3 = __expf(e3);
        denom += (w0 + w1) + (w2 + w3);
        acc.x += w0 * v0.x + w1 * v1.x + w2 * v2.x + w3 * v3.x;
        acc.y += w0 * v0.y + w1 * v1.y + w2 * v2.y + w3 * v3.y;
        acc.z += w0 * v0.z + w1 * v1.z + w2 * v2.z + w3 * v3.z;
        acc.w += w0 * v0.w + w1 * v1.w + w2 * v2.w + w3 * v3.w;
    }
    for (; j < end; j++) {
        int s = g_csr[j];
        float a = g_asrc[s * 4 + head];
        float e = a + adh; e = (e > 0.f) ? e : NEG_SLOPE * e;
        float4 v = h4[s * 32 + lane];
        float w = __expf(e);
        denom += w;
        acc.x += w * v.x; acc.y += w * v.y; acc.z += w * v.z; acc.w += w * v.w;
    }

    float inv = 1.0f / (denom + 1e-16f);
    float4 b  = ((const float4*)bias)[lane];
    float4 sk = ((const float4*)g_skip)[(size_t)n * 32 + lane];
    float4 o;
    o.x = acc.x * inv + b.x + sk.x;
    o.y = acc.y * inv + b.y + sk.y;
    o.z = acc.z * inv + b.z + sk.z;
    o.w = acc.w * inv + b.w + sk.w;
    o.x = (o.x > 0.f) ? o.x : expm1f(o.x);
    o.y = (o.y > 0.f) ? o.y : expm1f(o.y);
    o.z = (o.z > 0.f) ? o.z : expm1f(o.z);
    o.w = (o.w > 0.f) ? o.w : expm1f(o.w);
    ((float4*)out)[(size_t)n * 32 + lane] = o;
}

// ------------------- launch -------------------
extern "C" void kernel_launch(void* const* d_in, const int* in_sizes, int n_in,
                              void* d_out, int out_size) {
    const float* x    = (const float*)d_in[0];
    const int*   ei   = (const int*)  d_in[1];
    const float* W1   = (const float*)d_in[2];
    const float* as1  = (const float*)d_in[3];
    const float* ad1  = (const float*)d_in[4];
    const float* b1   = (const float*)d_in[5];
    const float* Ws1  = (const float*)d_in[6];
    const float* W2   = (const float*)d_in[7];
    const float* as2  = (const float*)d_in[8];
    const float* ad2  = (const float*)d_in[9];
    const float* b2   = (const float*)d_in[10];
    const float* Ws2  = (const float*)d_in[11];

    int N = in_sizes[0] / DIM;
    int E = in_sizes[1] / 2;
    const int* src = ei;
    const int* dst = ei + E;

    float* buf1;  cudaGetSymbolAddress((void**)&buf1, g_buf1);
    __nv_bfloat16* bhi; cudaGetSymbolAddress((void**)&bhi, g_bhi);
    __nv_bfloat16* blo; cudaGetSymbolAddress((void**)&blo, g_blo);

    const size_t dyn = 27136 * 4;
    cudaFuncSetAttribute(gat_mma_fused, cudaFuncAttributeMaxDynamicSharedMemorySize, (int)dyn);

    int nb = (N + SCAN_CHUNK - 1) / SCAN_CHUNK;
    int gemm_blocks = (N + 63) / 64;
    int warp_blocks = (N * 32 + 255) / 256;

    // launch idx:
    prep_hist<<<WPREP_BLKS + 1024, 256>>>(W1, Ws1, W2, Ws2, dst, E);         // 0
    scan_lookback<<<nb, 256>>>(N);                                           // 1
    gat_mma_fused<<<gemm_blocks + SCAT_BLKS, 256, dyn>>>(                    // 2 (gemm1+scatter)
        x, (const uint32_t*)bhi, (const uint32_t*)blo, as1, ad1, N,
        gemm_blocks, src, dst, E);
    agg_kernel<<<warp_blocks, 256>>>(b1, buf1, N);                           // 3 <- profiled
    gat_mma_fused<<<gemm_blocks, 256, dyn>>>(                                // 4 (gemm2)
        buf1, (const uint32_t*)(bhi + 256 * 128), (const uint32_t*)(blo + 256 * 128),
        as2, ad2, N, gemm_blocks, nullptr, nullptr, 0);
    agg_kernel<<<warp_blocks, 256>>>(b2, (float*)d_out, N);                  // 5
}

// round 14
// speedup vs baseline: 1.2472x; 1.0211x over previous
#include <cuda_runtime.h>
#include <cuda_bf16.h>
#include <stdint.h>
#include <math.h>

#define DIM 128
#define HEADS 4
#define NEG_SLOPE 0.2f
#define MAX_N 50000
#define MAX_E 600000
#define SCAN_CHUNK 1024
#define MAX_NB ((MAX_N + SCAN_CHUNK - 1) / SCAN_CHUNK)
#define WPREP_BLKS 256   // 65536 weight elems / 256 thr
#define SCAT_BLKS 1024   // scatter-role blocks appended to GEMM-1

// ------------------- scratch (static device globals; no allocs) -------------------
__device__ float g_h[(MAX_N + 1) * DIM];    // +1 sentinel row (zeroed)
__device__ float g_skip[MAX_N * DIM];
__device__ float g_buf1[MAX_N * DIM];
__device__ float g_asrc[(MAX_N + 1) * HEADS];  // +1 sentinel (-1e30)
__device__ float g_adst[MAX_N * HEADS];
__device__ int   g_deg[MAX_N];           // zero-invariant: scan re-zeroes after read
__device__ int   g_off[MAX_N + 1];       // PADDED segment starts (each multiple of 4)
__device__ int   g_cursor[MAX_N];
__device__ int   g_csr[MAX_E + 4 * MAX_N];  // padded CSR (sentinels in pad slots)
__device__ int   g_agg[MAX_NB];
__device__ int   g_flag[MAX_NB];         // zero-invariant: scatter role re-zeroes
// combined transposed weights per layer: Bt[n][k]: n<128 -> W[k][n], else Wskip[k][n-128]
__device__ __nv_bfloat16 g_bhi[2 * 256 * 128];
__device__ __nv_bfloat16 g_blo[2 * 256 * 128];

// ------------------- prep (weights + sentinels) + degree histogram, role-split -------
__global__ void prep_hist(const float* __restrict__ W1, const float* __restrict__ Ws1,
                          const float* __restrict__ W2, const float* __restrict__ Ws2,
                          const int* __restrict__ dst, int E, int N) {
    int tid = threadIdx.x;
    if ((int)blockIdx.x < WPREP_BLKS) {
        if (blockIdx.x == 0) {   // sentinel init (once per replay; deterministic)
            if (tid < 128) g_h[(size_t)N * 128 + tid] = 0.0f;
            if (tid >= 128 && tid < 132) g_asrc[N * 4 + (tid - 128)] = -1e30f;
        }
        int idx = blockIdx.x * 256 + tid;                 // 0..65535
        int layer = idx >> 15;
        int rem   = idx & 32767;
        int n     = rem >> 7;
        int k     = rem & 127;
        const float* W = layer ? (n < 128 ? W2 : Ws2) : (n < 128 ? W1 : Ws1);
        float v = W[k * 128 + (n & 127)];
        __nv_bfloat16 hi = __float2bfloat16(v);
        float lo = v - __bfloat162float(hi);
        g_bhi[idx] = hi;
        g_blo[idx] = __float2bfloat16(lo);
    } else {
        int nbh = gridDim.x - WPREP_BLKS;
        for (int i = (blockIdx.x - WPREP_BLKS) * 256 + tid; i < E; i += nbh * 256)
            atomicAdd(&g_deg[dst[i]], 1);
    }
}

// ------------------- scan (padded-to-4 segments) with decoupled lookback -------------
// Writes: g_cursor (real-entry start), g_off (padded starts), sentinel pad entries.
__global__ void scan_lookback(int N) {
    __shared__ int wsum[8];
    __shared__ int s_base;
    int tid = threadIdx.x;
    int lane = tid & 31, warp = tid >> 5;
    int b = blockIdx.x;
    int i0 = b * SCAN_CHUNK + tid * 4;

    int4 d = make_int4(0, 0, 0, 0);
    if (i0 + 3 < N) {
        d = *(const int4*)(g_deg + i0);
        *(int4*)(g_deg + i0) = make_int4(0, 0, 0, 0);
        d.x += 1; d.y += 1; d.z += 1; d.w += 1;   // self-loops
    } else {
        if (i0 + 0 < N) { d.x = g_deg[i0 + 0] + 1; g_deg[i0 + 0] = 0; }
        if (i0 + 1 < N) { d.y = g_deg[i0 + 1] + 1; g_deg[i0 + 1] = 0; }
        if (i0 + 2 < N) { d.z = g_deg[i0 + 2] + 1; g_deg[i0 + 2] = 0; }
        if (i0 + 3 < N) { d.w = g_deg[i0 + 3] + 1; g_deg[i0 + 3] = 0; }
    }
    int4 p;   // padded lengths
    p.x = (d.x + 3) & ~3;
    p.y = (d.y + 3) & ~3;
    p.z = (d.z + 3) & ~3;
    p.w = (d.w + 3) & ~3;
    int T = p.x + p.y + p.z + p.w;
    int v = T;
    #pragma unroll
    for (int o = 1; o < 32; o <<= 1) {
        int t = __shfl_up_sync(0xffffffffu, v, o);
        if (lane >= o) v += t;
    }
    if (lane == 31) wsum[warp] = v;
    __syncthreads();
    if (warp == 0) {
        int w = (lane < 8) ? wsum[lane] : 0;
        #pragma unroll
        for (int o = 1; o < 8; o <<= 1) {
            int t = __shfl_up_sync(0xffffffffu, w, o);
            if (lane >= o) w += t;
        }
        if (lane < 8) wsum[lane] = w;
        if (lane == 0) {
            g_agg[b] = wsum[7];
            __threadfence();
            atomicExch(&g_flag[b], 1);
        }
    }
    __syncthreads();
    int blk_scan = (warp ? wsum[warp - 1] : 0);

    if (warp == 0) {
        int base = 0;
        for (int i = lane; i < b; i += 32) {
            while (atomicAdd(&g_flag[i], 0) == 0) {}
            base += g_agg[i];
        }
        #pragma unroll
        for (int o = 16; o > 0; o >>= 1) base += __shfl_xor_sync(0xffffffffu, base, o);
        if (lane == 0) s_base = base;
    }
    __syncthreads();

    int excl = v - T + blk_scan + s_base;
    int cur = excl;
    #pragma unroll
    for (int q = 0; q < 4; q++) {
        int i = i0 + q;
        int dd = (q == 0) ? d.x : (q == 1) ? d.y : (q == 2) ? d.z : d.w;
        int pp = (q == 0) ? p.x : (q == 1) ? p.y : (q == 2) ? p.z : p.w;
        if (i < N) {
            g_cursor[i] = cur;
            g_off[i + 1] = cur + pp;
            for (int k = dd; k < pp; k++) g_csr[cur + k] = N;   // sentinel pads
            cur += pp;
        }
    }
    if (b == 0 && tid == 0) g_off[0] = 0;
}

// ------------------- MMA / ldmatrix helpers -------------------
__device__ __forceinline__ void mma_bf16(float c[4], const uint32_t a[4],
                                         uint32_t b0, uint32_t b1) {
    asm volatile(
        "mma.sync.aligned.m16n8k16.row.col.f32.bf16.bf16.f32 "
        "{%0,%1,%2,%3}, {%4,%5,%6,%7}, {%8,%9}, {%0,%1,%2,%3};"
        : "+f"(c[0]), "+f"(c[1]), "+f"(c[2]), "+f"(c[3])
        : "r"(a[0]), "r"(a[1]), "r"(a[2]), "r"(a[3]), "r"(b0), "r"(b1));
}
__device__ __forceinline__ void ldsm_x4(uint32_t d[4], uint32_t addr) {
    asm volatile("ldmatrix.sync.aligned.m8n8.x4.shared.b16 {%0,%1,%2,%3}, [%4];"
                 : "=r"(d[0]), "=r"(d[1]), "=r"(d[2]), "=r"(d[3]) : "r"(addr));
}
__device__ __forceinline__ uint32_t s2u(const void* p) {
    return (uint32_t)__cvta_generic_to_shared(p);
}
__device__ __forceinline__ uint32_t pack_bf16hi(float a, float b) {
    return ((uint32_t)__bfloat16_as_ushort(__float2bfloat16(b)) << 16)
         | __bfloat16_as_ushort(__float2bfloat16(a));
}

// ------------------- fused HMMA GEMM (h + skip) + att logits [+ scatter side-blocks] --
__global__ void __launch_bounds__(256, 2)
gat_mma_fused(const float* __restrict__ X,
              const uint32_t* __restrict__ Bhi, const uint32_t* __restrict__ Blo,
              const float* __restrict__ a_src, const float* __restrict__ a_dst,
              int nrows, int gemm_nb,
              const int* __restrict__ srcE, const int* __restrict__ dstE, int E) {
    int tid = threadIdx.x;

    if ((int)blockIdx.x >= gemm_nb) {   // ---- scatter role ----
        int nbs = gridDim.x - gemm_nb;
        int base = (blockIdx.x - gemm_nb) * 256 + tid;
        if (base < MAX_NB) g_flag[base] = 0;   // reset lookback flags for next replay
        for (int i = base; i < E + nrows; i += nbs * 256) {
            int s, dn;
            if (i < E) { s = srcE[i]; dn = dstE[i]; }
            else       { s = dn = i - E; }
            int p = atomicAdd(&g_cursor[dn], 1);
            g_csr[p] = s;
        }
        return;
    }

    extern __shared__ uint32_t dsm[];
    __shared__ float s_att[256];
    uint32_t* Ah = dsm;            // 64*68
    uint32_t* Al = dsm + 4352;
    uint32_t* Bh = dsm + 8704;     // 256*36
    uint32_t* Bl = dsm + 17920;

    int row0 = blockIdx.x * 64;
    if (tid < 128) { s_att[tid] = a_src[tid]; s_att[128 + tid] = a_dst[tid]; }

    // A staging: 2048 float4 loads across 256 thr = 8 iters
    #pragma unroll
    for (int it = 0; it < 8; it++) {
        int idx = tid + it * 256;          // 0..2047
        int r = idx >> 5;                  // row
        int c4 = idx & 31;                 // float4 index in row
        float4 xv = make_float4(0.f, 0.f, 0.f, 0.f);
        int gr = row0 + r;
        if (gr < nrows)
            xv = *(const float4*)(X + (size_t)gr * 128 + c4 * 4);
        uint32_t h0 = pack_bf16hi(xv.x, xv.y);
        uint32_t h1 = pack_bf16hi(xv.z, xv.w);
        float lx = xv.x - __bfloat162float(__float2bfloat16(xv.x));
        float ly = xv.y - __bfloat162float(__float2bfloat16(xv.y));
        float lz = xv.z - __bfloat162float(__float2bfloat16(xv.z));
        float lw = xv.w - __bfloat162float(__float2bfloat16(xv.w));
        uint32_t l0 = pack_bf16hi(lx, ly);
        uint32_t l1 = pack_bf16hi(lz, lw);
        int w = c4 * 2;
        *(uint2*)(Ah + r * 68 + w) = make_uint2(h0, h1);
        *(uint2*)(Al + r * 68 + w) = make_uint2(l0, l1);
    }

    int lane = tid & 31, warp = tid >> 5;
    int mi = warp & 1, ni = warp >> 1;
    int g = lane >> 2, t = lane & 3;
    int mloc  = mi * 32;
    int nbase = ni * 64;

    uint32_t a_off = (uint32_t)(((mloc + (lane & 15)) * 68 + ((lane >> 4) << 2)) * 4);
    uint32_t ah_base = s2u(Ah) + a_off;
    uint32_t al_base = s2u(Al) + a_off;
    uint32_t b_off = (uint32_t)((((nbase + ((lane >> 4) << 3) + (lane & 7)) * 36)
                                 + (((lane >> 3) & 1) << 2)) * 4);
    uint32_t bh_base = s2u(Bh) + b_off;
    uint32_t bl_base = s2u(Bl) + b_off;

    float acc[2][8][4];
    #pragma unroll
    for (int a = 0; a < 2; a++)
        #pragma unroll
        for (int b = 0; b < 8; b++)
            #pragma unroll
            for (int c = 0; c < 4; c++) acc[a][b][c] = 0.f;

    for (int kc = 0; kc < 2; kc++) {
        if (kc) __syncthreads();
        // B staging: 4096 uint2 per array across 256 thr = 16 iters
        #pragma unroll
        for (int it = 0; it < 16; it++) {
            int idx = tid + it * 256;      // 0..4095
            int r = idx >> 4;              // row (256 rows)
            int w = (idx & 15) * 2;        // word pair
            *(uint2*)(Bh + r * 36 + w) = *(const uint2*)(Bhi + r * 64 + kc * 32 + w);
            *(uint2*)(Bl + r * 36 + w) = *(const uint2*)(Blo + r * 64 + kc * 32 + w);
        }
        __syncthreads();

        #pragma unroll
        for (int ksl = 0; ksl < 4; ksl++) {
            uint32_t kb = (uint32_t)((kc * 32 + ksl * 8) * 4);
            uint32_t bb = (uint32_t)((ksl * 8) * 4);
            uint32_t ah[2][4], al[2][4], bf[4][4];
            ldsm_x4(ah[0], ah_base + kb);
            ldsm_x4(ah[1], ah_base + kb + 16 * 68 * 4);
            ldsm_x4(al[0], al_base + kb);
            ldsm_x4(al[1], al_base + kb + 16 * 68 * 4);
            #pragma unroll
            for (int q = 0; q < 4; q++)
                ldsm_x4(bf[q], bh_base + bb + (uint32_t)(q * 16 * 36 * 4));
            #pragma unroll
            for (int q = 0; q < 4; q++) {
                mma_bf16(acc[0][2 * q],     ah[0], bf[q][0], bf[q][1]);
                mma_bf16(acc[1][2 * q],     ah[1], bf[q][0], bf[q][1]);
                mma_bf16(acc[0][2 * q + 1], ah[0], bf[q][2], bf[q][3]);
                mma_bf16(acc[1][2 * q + 1], ah[1], bf[q][2], bf[q][3]);
            }
            #pragma unroll
            for (int q = 0; q < 4; q++) {
                mma_bf16(acc[0][2 * q],     al[0], bf[q][0], bf[q][1]);
                mma_bf16(acc[1][2 * q],     al[1], bf[q][0], bf[q][1]);
                mma_bf16(acc[0][2 * q + 1], al[0], bf[q][2], bf[q][3]);
                mma_bf16(acc[1][2 * q + 1], al[1], bf[q][2], bf[q][3]);
            }
            #pragma unroll
            for (int q = 0; q < 4; q++)
                ldsm_x4(bf[q], bl_base + bb + (uint32_t)(q * 16 * 36 * 4));
            #pragma unroll
            for (int q = 0; q < 4; q++) {
                mma_bf16(acc[0][2 * q],     ah[0], bf[q][0], bf[q][1]);
                mma_bf16(acc[1][2 * q],     ah[1], bf[q][0], bf[q][1]);
                mma_bf16(acc[0][2 * q + 1], ah[0], bf[q][2], bf[q][3]);
                mma_bf16(acc[1][2 * q + 1], ah[1], bf[q][2], bf[q][3]);
            }
        }
    }

    int gr0 = row0 + mloc;
    if (ni < 2) {
        float ps[2][2][2], pd[2][2][2];
        #pragma unroll
        for (int a = 0; a < 2; a++)
            #pragma unroll
            for (int b = 0; b < 2; b++) {
                ps[a][b][0] = ps[a][b][1] = 0.f;
                pd[a][b][0] = pd[a][b][1] = 0.f;
            }
        #pragma unroll
        for (int mt = 0; mt < 2; mt++) {
            int r0 = gr0 + mt * 16 + g;
            int r1 = r0 + 8;
            #pragma unroll
            for (int nt = 0; nt < 8; nt++) {
                int col = nbase + nt * 8 + t * 2;
                int hh = nt >> 2;
                float s0 = s_att[col],       s1 = s_att[col + 1];
                float d0 = s_att[128 + col], d1 = s_att[128 + col + 1];
                ps[mt][0][hh] += acc[mt][nt][0] * s0 + acc[mt][nt][1] * s1;
                pd[mt][0][hh] += acc[mt][nt][0] * d0 + acc[mt][nt][1] * d1;
                ps[mt][1][hh] += acc[mt][nt][2] * s0 + acc[mt][nt][3] * s1;
                pd[mt][1][hh] += acc[mt][nt][2] * d0 + acc[mt][nt][3] * d1;
                if (r0 < nrows)
                    *(float2*)(g_h + (size_t)r0 * 128 + col) =
                        make_float2(acc[mt][nt][0], acc[mt][nt][1]);
                if (r1 < nrows)
                    *(float2*)(g_h + (size_t)r1 * 128 + col) =
                        make_float2(acc[mt][nt][2], acc[mt][nt][3]);
            }
        }
        #pragma unroll
        for (int mt = 0; mt < 2; mt++)
            #pragma unroll
            for (int rs = 0; rs < 2; rs++)
                #pragma unroll
                for (int hh = 0; hh < 2; hh++) {
                    float vs = ps[mt][rs][hh];
                    float vd = pd[mt][rs][hh];
                    vs += __shfl_xor_sync(0xffffffffu, vs, 1);
                    vs += __shfl_xor_sync(0xffffffffu, vs, 2);
                    vd += __shfl_xor_sync(0xffffffffu, vd, 1);
                    vd += __shfl_xor_sync(0xffffffffu, vd, 2);
                    if (t == 0) {
                        int r = gr0 + mt * 16 + g + rs * 8;
                        if (r < nrows) {
                            int head = ni * 2 + hh;
                            g_asrc[r * 4 + head] = vs;
                            g_adst[r * 4 + head] = vd;
                        }
                    }
                }
    } else {
        int cb = nbase - 128;
        #pragma unroll
        for (int mt = 0; mt < 2; mt++) {
            int r0 = gr0 + mt * 16 + g;
            int r1 = r0 + 8;
            #pragma unroll
            for (int nt = 0; nt < 8; nt++) {
                int col = cb + nt * 8 + t * 2;
                if (r0 < nrows)
                    *(float2*)(g_skip + (size_t)r0 * 128 + col) =
                        make_float2(acc[mt][nt][0], acc[mt][nt][1]);
                if (r1 < nrows)
                    *(float2*)(g_skip + (size_t)r1 * 128 + col) =
                        make_float2(acc[mt][nt][2], acc[mt][nt][3]);
            }
        }
    }
}

// ------------------- softmax aggregate: padded CSR (int4), no-max exp ----------------
__global__ void __launch_bounds__(256)
agg_kernel(const float* __restrict__ bias, float* __restrict__ out, int N) {
    int gw = (blockIdx.x * blockDim.x + threadIdx.x) >> 5;
    int lane = threadIdx.x & 31;
    if (gw >= N) return;
    int n = gw;
    int beg = g_off[n];
    int end = g_off[n + 1];   // padded; (end-beg) % 4 == 0, >= 4
    int head = lane >> 3;

    float adh = g_adst[n * 4 + head];
    const float4* h4 = (const float4*)g_h;

    float denom = 0.0f;
    float4 acc = make_float4(0.f, 0.f, 0.f, 0.f);

    for (int j = beg; j < end; j += 4) {
        int4 s4 = *(const int4*)(g_csr + j);   // aligned (beg % 4 == 0)
        float a0 = g_asrc[s4.x * 4 + head];
        float a1 = g_asrc[s4.y * 4 + head];
        float a2 = g_asrc[s4.z * 4 + head];
        float a3 = g_asrc[s4.w * 4 + head];
        float4 v0 = h4[s4.x * 32 + lane];
        float4 v1 = h4[s4.y * 32 + lane];
        float4 v2 = h4[s4.z * 32 + lane];
        float4 v3 = h4[s4.w * 32 + lane];

        float e0 = a0 + adh; e0 = (e0 > 0.f) ? e0 : NEG_SLOPE * e0;
        float e1 = a1 + adh; e1 = (e1 > 0.f) ? e1 : NEG_SLOPE * e1;
        float e2 = a2 + adh; e2 = (e2 > 0.f) ? e2 : NEG_SLOPE * e2;
        float e3 = a3 + adh; e3 = (e3 > 0.f) ? e3 : NEG_SLOPE * e3;

        float w0 = __expf(e0);   // sentinel: e = -2e29 -> w = 0
        float w1 = __expf(e1);
        float w2 = __expf(e2);
        float w3 = __expf(e3);
        denom += (w0 + w1) + (w2 + w3);
        acc.x += w0 * v0.x + w1 * v1.x + w2 * v2.x + w3 * v3.x;
        acc.y += w0 * v0.y + w1 * v1.y + w2 * v2.y + w3 * v3.y;
        acc.z += w0 * v0.z + w1 * v1.z + w2 * v2.z + w3 * v3.z;
        acc.w += w0 * v0.w + w1 * v1.w + w2 * v2.w + w3 * v3.w;
    }

    float inv = 1.0f / (denom + 1e-16f);
    float4 b  = ((const float4*)bias)[lane];
    float4 sk = ((const float4*)g_skip)[(size_t)n * 32 + lane];
    float4 o;
    o.x = acc.x * inv + b.x + sk.x;
    o.y = acc.y * inv + b.y + sk.y;
    o.z = acc.z * inv + b.z + sk.z;
    o.w = acc.w * inv + b.w + sk.w;
    o.x = (o.x > 0.f) ? o.x : expm1f(o.x);
    o.y = (o.y > 0.f) ? o.y : expm1f(o.y);
    o.z = (o.z > 0.f) ? o.z : expm1f(o.z);
    o.w = (o.w > 0.f) ? o.w : expm1f(o.w);
    ((float4*)out)[(size_t)n * 32 + lane] = o;
}

// ------------------- launch -------------------
extern "C" void kernel_launch(void* const* d_in, const int* in_sizes, int n_in,
                              void* d_out, int out_size) {
    const float* x    = (const float*)d_in[0];
    const int*   ei   = (const int*)  d_in[1];
    const float* W1   = (const float*)d_in[2];
    const float* as1  = (const float*)d_in[3];
    const float* ad1  = (const float*)d_in[4];
    const float* b1   = (const float*)d_in[5];
    const float* Ws1  = (const float*)d_in[6];
    const float* W2   = (const float*)d_in[7];
    const float* as2  = (const float*)d_in[8];
    const float* ad2  = (const float*)d_in[9];
    const float* b2   = (const float*)d_in[10];
    const float* Ws2  = (const float*)d_in[11];

    int N = in_sizes[0] / DIM;
    int E = in_sizes[1] / 2;
    const int* src = ei;
    const int* dst = ei + E;

    float* buf1;  cudaGetSymbolAddress((void**)&buf1, g_buf1);
    __nv_bfloat16* bhi; cudaGetSymbolAddress((void**)&bhi, g_bhi);
    __nv_bfloat16* blo; cudaGetSymbolAddress((void**)&blo, g_blo);

    const size_t dyn = 27136 * 4;
    cudaFuncSetAttribute(gat_mma_fused, cudaFuncAttributeMaxDynamicSharedMemorySize, (int)dyn);

    int nb = (N + SCAN_CHUNK - 1) / SCAN_CHUNK;
    int gemm_blocks = (N + 63) / 64;
    int warp_blocks = (N * 32 + 255) / 256;

    // launch idx:
    prep_hist<<<WPREP_BLKS + 1024, 256>>>(W1, Ws1, W2, Ws2, dst, E, N);      // 0
    scan_lookback<<<nb, 256>>>(N);                                           // 1
    gat_mma_fused<<<gemm_blocks + SCAT_BLKS, 256, dyn>>>(                    // 2 (gemm1+scatter)
        x, (const uint32_t*)bhi, (const uint32_t*)blo, as1, ad1, N,
        gemm_blocks, src, dst, E);
    agg_kernel<<<warp_blocks, 256>>>(b1, buf1, N);                           // 3 <- profiled
    gat_mma_fused<<<gemm_blocks, 256, dyn>>>(                                // 4 (gemm2)
        buf1, (const uint32_t*)(bhi + 256 * 128), (const uint32_t*)(blo + 256 * 128),
        as2, ad2, N, gemm_blocks, nullptr, nullptr, 0);
    agg_kernel<<<warp_blocks, 256>>>(b2, (float*)d_out, N);                  // 5
}

// round 15
// speedup vs baseline: 1.2650x; 1.0143x over previous
#include <cuda_runtime.h>
#include <cuda_bf16.h>
#include <stdint.h>
#include <math.h>

#define DIM 128
#define HEADS 4
#define NEG_SLOPE 0.2f
#define MAX_N 50000
#define MAX_E 600000
#define SCAN_CHUNK 1024
#define MAX_NB ((MAX_N + SCAN_CHUNK - 1) / SCAN_CHUNK)
#define WPREP_BLKS 256   // 65536 weight elems / 256 thr
#define SCAT_BLKS 1024   // scatter-role blocks appended to GEMM-1

// ------------------- scratch (static device globals; no allocs) -------------------
__device__ float g_h[MAX_N * DIM];
__device__ float g_skip[MAX_N * DIM];
__device__ float g_buf1[MAX_N * DIM];
__device__ float g_asrc[MAX_N * HEADS];
__device__ float g_adst[MAX_N * HEADS];
__device__ int   g_deg[MAX_N];           // zero-invariant: scan re-zeroes after read
__device__ int   g_off[MAX_N + 1];
__device__ int   g_cursor[MAX_N];
__device__ int   g_csr[MAX_E + MAX_N];
__device__ int   g_agg[MAX_NB];
__device__ int   g_flag[MAX_NB];         // zero-invariant: scatter role re-zeroes
// combined transposed weights per layer: Bt[n][k]: n<128 -> W[k][n], else Wskip[k][n-128]
__device__ __nv_bfloat16 g_bhi[2 * 256 * 128];
__device__ __nv_bfloat16 g_blo[2 * 256 * 128];

// ------------------- prep (weights) + degree histogram, role-split -------------------
__global__ void prep_hist(const float* __restrict__ W1, const float* __restrict__ Ws1,
                          const float* __restrict__ W2, const float* __restrict__ Ws2,
                          const int* __restrict__ dst, int E) {
    int tid = threadIdx.x;
    if ((int)blockIdx.x < WPREP_BLKS) {
        int idx = blockIdx.x * 256 + tid;                 // 0..65535
        int layer = idx >> 15;
        int rem   = idx & 32767;
        int n     = rem >> 7;
        int k     = rem & 127;
        const float* W = layer ? (n < 128 ? W2 : Ws2) : (n < 128 ? W1 : Ws1);
        float v = W[k * 128 + (n & 127)];
        __nv_bfloat16 hi = __float2bfloat16(v);
        float lo = v - __bfloat162float(hi);
        g_bhi[idx] = hi;
        g_blo[idx] = __float2bfloat16(lo);
    } else {
        int nbh = gridDim.x - WPREP_BLKS;
        for (int i = (blockIdx.x - WPREP_BLKS) * 256 + tid; i < E; i += nbh * 256)
            atomicAdd(&g_deg[dst[i]], 1);
    }
}

// ------------------- single-kernel scan with decoupled lookback -------------------
__global__ void scan_lookback(int N) {
    __shared__ int wsum[8];
    __shared__ int s_base;
    int tid = threadIdx.x;
    int lane = tid & 31, warp = tid >> 5;
    int b = blockIdx.x;
    int i0 = b * SCAN_CHUNK + tid * 4;

    int4 d = make_int4(0, 0, 0, 0);
    if (i0 + 3 < N) {
        d = *(const int4*)(g_deg + i0);
        *(int4*)(g_deg + i0) = make_int4(0, 0, 0, 0);
        d.x += 1; d.y += 1; d.z += 1; d.w += 1;   // self-loops
    } else {
        if (i0 + 0 < N) { d.x = g_deg[i0 + 0] + 1; g_deg[i0 + 0] = 0; }
        if (i0 + 1 < N) { d.y = g_deg[i0 + 1] + 1; g_deg[i0 + 1] = 0; }
        if (i0 + 2 < N) { d.z = g_deg[i0 + 2] + 1; g_deg[i0 + 2] = 0; }
        if (i0 + 3 < N) { d.w = g_deg[i0 + 3] + 1; g_deg[i0 + 3] = 0; }
    }
    int T = d.x + d.y + d.z + d.w;
    int v = T;
    #pragma unroll
    for (int o = 1; o < 32; o <<= 1) {
        int t = __shfl_up_sync(0xffffffffu, v, o);
        if (lane >= o) v += t;
    }
    if (lane == 31) wsum[warp] = v;
    __syncthreads();
    if (warp == 0) {
        int w = (lane < 8) ? wsum[lane] : 0;
        #pragma unroll
        for (int o = 1; o < 8; o <<= 1) {
            int t = __shfl_up_sync(0xffffffffu, w, o);
            if (lane >= o) w += t;
        }
        if (lane < 8) wsum[lane] = w;
        if (lane == 0) {
            g_agg[b] = wsum[7];
            __threadfence();
            atomicExch(&g_flag[b], 1);
        }
    }
    __syncthreads();
    int blk_scan = (warp ? wsum[warp - 1] : 0);

    if (warp == 0) {
        int base = 0;
        for (int i = lane; i < b; i += 32) {
            while (atomicAdd(&g_flag[i], 0) == 0) {}
            base += g_agg[i];
        }
        #pragma unroll
        for (int o = 16; o > 0; o >>= 1) base += __shfl_xor_sync(0xffffffffu, base, o);
        if (lane == 0) s_base = base;
    }
    __syncthreads();

    int excl = v - T + blk_scan + s_base;
    int p = excl;
    if (i0 + 0 < N) { g_cursor[i0 + 0] = p; g_off[i0 + 1] = p + d.x; p += d.x; }
    if (i0 + 1 < N) { g_cursor[i0 + 1] = p; g_off[i0 + 2] = p + d.y; p += d.y; }
    if (i0 + 2 < N) { g_cursor[i0 + 2] = p; g_off[i0 + 3] = p + d.z; p += d.z; }
    if (i0 + 3 < N) { g_cursor[i0 + 3] = p; g_off[i0 + 4] = p + d.w; }
    if (b == 0 && tid == 0) g_off[0] = 0;
}

// ------------------- MMA / ldmatrix helpers -------------------
__device__ __forceinline__ void mma_bf16(float c[4], const uint32_t a[4],
                                         uint32_t b0, uint32_t b1) {
    asm volatile(
        "mma.sync.aligned.m16n8k16.row.col.f32.bf16.bf16.f32 "
        "{%0,%1,%2,%3}, {%4,%5,%6,%7}, {%8,%9}, {%0,%1,%2,%3};"
        : "+f"(c[0]), "+f"(c[1]), "+f"(c[2]), "+f"(c[3])
        : "r"(a[0]), "r"(a[1]), "r"(a[2]), "r"(a[3]), "r"(b0), "r"(b1));
}
__device__ __forceinline__ void ldsm_x4(uint32_t d[4], uint32_t addr) {
    asm volatile("ldmatrix.sync.aligned.m8n8.x4.shared.b16 {%0,%1,%2,%3}, [%4];"
                 : "=r"(d[0]), "=r"(d[1]), "=r"(d[2]), "=r"(d[3]) : "r"(addr));
}
__device__ __forceinline__ uint32_t s2u(const void* p) {
    return (uint32_t)__cvta_generic_to_shared(p);
}
__device__ __forceinline__ uint32_t pack_bf16hi(float a, float b) {
    return ((uint32_t)__bfloat16_as_ushort(__float2bfloat16(b)) << 16)
         | __bfloat16_as_ushort(__float2bfloat16(a));
}

// ------------------- fused HMMA GEMM (h + skip) + att logits [+ scatter side-blocks] --
__global__ void __launch_bounds__(256, 2)
gat_mma_fused(const float* __restrict__ X,
              const uint32_t* __restrict__ Bhi, const uint32_t* __restrict__ Blo,
              const float* __restrict__ a_src, const float* __restrict__ a_dst,
              int nrows, int gemm_nb,
              const int* __restrict__ srcE, const int* __restrict__ dstE, int E) {
    int tid = threadIdx.x;

    if ((int)blockIdx.x >= gemm_nb) {   // ---- scatter role ----
        int nbs = gridDim.x - gemm_nb;
        int base = (blockIdx.x - gemm_nb) * 256 + tid;
        if (base < MAX_NB) g_flag[base] = 0;   // reset lookback flags for next replay
        for (int i = base; i < E + nrows; i += nbs * 256) {
            int s, dn;
            if (i < E) { s = srcE[i]; dn = dstE[i]; }
            else       { s = dn = i - E; }
            int p = atomicAdd(&g_cursor[dn], 1);
            g_csr[p] = s;
        }
        return;
    }

    extern __shared__ uint32_t dsm[];
    __shared__ float s_att[256];
    uint32_t* Ah = dsm;            // 64*68
    uint32_t* Al = dsm + 4352;
    uint32_t* Bh = dsm + 8704;     // 256*36
    uint32_t* Bl = dsm + 17920;

    int row0 = blockIdx.x * 64;
    if (tid < 128) { s_att[tid] = a_src[tid]; s_att[128 + tid] = a_dst[tid]; }

    // A staging: 2048 float4 loads across 256 thr = 8 iters
    #pragma unroll
    for (int it = 0; it < 8; it++) {
        int idx = tid + it * 256;          // 0..2047
        int r = idx >> 5;                  // row
        int c4 = idx & 31;                 // float4 index in row
        float4 xv = make_float4(0.f, 0.f, 0.f, 0.f);
        int gr = row0 + r;
        if (gr < nrows)
            xv = *(const float4*)(X + (size_t)gr * 128 + c4 * 4);
        uint32_t h0 = pack_bf16hi(xv.x, xv.y);
        uint32_t h1 = pack_bf16hi(xv.z, xv.w);
        float lx = xv.x - __bfloat162float(__float2bfloat16(xv.x));
        float ly = xv.y - __bfloat162float(__float2bfloat16(xv.y));
        float lz = xv.z - __bfloat162float(__float2bfloat16(xv.z));
        float lw = xv.w - __bfloat162float(__float2bfloat16(xv.w));
        uint32_t l0 = pack_bf16hi(lx, ly);
        uint32_t l1 = pack_bf16hi(lz, lw);
        int w = c4 * 2;
        *(uint2*)(Ah + r * 68 + w) = make_uint2(h0, h1);
        *(uint2*)(Al + r * 68 + w) = make_uint2(l0, l1);
    }

    int lane = tid & 31, warp = tid >> 5;
    int mi = warp & 1, ni = warp >> 1;
    int g = lane >> 2, t = lane & 3;
    int mloc  = mi * 32;
    int nbase = ni * 64;

    uint32_t a_off = (uint32_t)(((mloc + (lane & 15)) * 68 + ((lane >> 4) << 2)) * 4);
    uint32_t ah_base = s2u(Ah) + a_off;
    uint32_t al_base = s2u(Al) + a_off;
    uint32_t b_off = (uint32_t)((((nbase + ((lane >> 4) << 3) + (lane & 7)) * 36)
                                 + (((lane >> 3) & 1) << 2)) * 4);
    uint32_t bh_base = s2u(Bh) + b_off;
    uint32_t bl_base = s2u(Bl) + b_off;

    float acc[2][8][4];
    #pragma unroll
    for (int a = 0; a < 2; a++)
        #pragma unroll
        for (int b = 0; b < 8; b++)
            #pragma unroll
            for (int c = 0; c < 4; c++) acc[a][b][c] = 0.f;

    for (int kc = 0; kc < 2; kc++) {
        if (kc) __syncthreads();
        // B staging: 4096 uint2 per array across 256 thr = 16 iters
        #pragma unroll
        for (int it = 0; it < 16; it++) {
            int idx = tid + it * 256;      // 0..4095
            int r = idx >> 4;              // row (256 rows)
            int w = (idx & 15) * 2;        // word pair
            *(uint2*)(Bh + r * 36 + w) = *(const uint2*)(Bhi + r * 64 + kc * 32 + w);
            *(uint2*)(Bl + r * 36 + w) = *(const uint2*)(Blo + r * 64 + kc * 32 + w);
        }
        __syncthreads();

        #pragma unroll
        for (int ksl = 0; ksl < 4; ksl++) {
            uint32_t kb = (uint32_t)((kc * 32 + ksl * 8) * 4);
            uint32_t bb = (uint32_t)((ksl * 8) * 4);
            uint32_t ah[2][4], al[2][4], bf[4][4];
            ldsm_x4(ah[0], ah_base + kb);
            ldsm_x4(ah[1], ah_base + kb + 16 * 68 * 4);
            ldsm_x4(al[0], al_base + kb);
            ldsm_x4(al[1], al_base + kb + 16 * 68 * 4);
            #pragma unroll
            for (int q = 0; q < 4; q++)
                ldsm_x4(bf[q], bh_base + bb + (uint32_t)(q * 16 * 36 * 4));
            #pragma unroll
            for (int q = 0; q < 4; q++) {
                mma_bf16(acc[0][2 * q],     ah[0], bf[q][0], bf[q][1]);
                mma_bf16(acc[1][2 * q],     ah[1], bf[q][0], bf[q][1]);
                mma_bf16(acc[0][2 * q + 1], ah[0], bf[q][2], bf[q][3]);
                mma_bf16(acc[1][2 * q + 1], ah[1], bf[q][2], bf[q][3]);
            }
            #pragma unroll
            for (int q = 0; q < 4; q++) {
                mma_bf16(acc[0][2 * q],     al[0], bf[q][0], bf[q][1]);
                mma_bf16(acc[1][2 * q],     al[1], bf[q][0], bf[q][1]);
                mma_bf16(acc[0][2 * q + 1], al[0], bf[q][2], bf[q][3]);
                mma_bf16(acc[1][2 * q + 1], al[1], bf[q][2], bf[q][3]);
            }
            #pragma unroll
            for (int q = 0; q < 4; q++)
                ldsm_x4(bf[q], bl_base + bb + (uint32_t)(q * 16 * 36 * 4));
            #pragma unroll
            for (int q = 0; q < 4; q++) {
                mma_bf16(acc[0][2 * q],     ah[0], bf[q][0], bf[q][1]);
                mma_bf16(acc[1][2 * q],     ah[1], bf[q][0], bf[q][1]);
                mma_bf16(acc[0][2 * q + 1], ah[0], bf[q][2], bf[q][3]);
                mma_bf16(acc[1][2 * q + 1], ah[1], bf[q][2], bf[q][3]);
            }
        }
    }

    int gr0 = row0 + mloc;
    if (ni < 2) {
        float ps[2][2][2], pd[2][2][2];
        #pragma unroll
        for (int a = 0; a < 2; a++)
            #pragma unroll
            for (int b = 0; b < 2; b++) {
                ps[a][b][0] = ps[a][b][1] = 0.f;
                pd[a][b][0] = pd[a][b][1] = 0.f;
            }
        #pragma unroll
        for (int mt = 0; mt < 2; mt++) {
            int r0 = gr0 + mt * 16 + g;
            int r1 = r0 + 8;
            #pragma unroll
            for (int nt = 0; nt < 8; nt++) {
                int col = nbase + nt * 8 + t * 2;
                int hh = nt >> 2;
                float s0 = s_att[col],       s1 = s_att[col + 1];
                float d0 = s_att[128 + col], d1 = s_att[128 + col + 1];
                ps[mt][0][hh] += acc[mt][nt][0] * s0 + acc[mt][nt][1] * s1;
                pd[mt][0][hh] += acc[mt][nt][0] * d0 + acc[mt][nt][1] * d1;
                ps[mt][1][hh] += acc[mt][nt][2] * s0 + acc[mt][nt][3] * s1;
                pd[mt][1][hh] += acc[mt][nt][2] * d0 + acc[mt][nt][3] * d1;
                if (r0 < nrows)
                    *(float2*)(g_h + (size_t)r0 * 128 + col) =
                        make_float2(acc[mt][nt][0], acc[mt][nt][1]);
                if (r1 < nrows)
                    *(float2*)(g_h + (size_t)r1 * 128 + col) =
                        make_float2(acc[mt][nt][2], acc[mt][nt][3]);
            }
        }
        #pragma unroll
        for (int mt = 0; mt < 2; mt++)
            #pragma unroll
            for (int rs = 0; rs < 2; rs++)
                #pragma unroll
                for (int hh = 0; hh < 2; hh++) {
                    float vs = ps[mt][rs][hh];
                    float vd = pd[mt][rs][hh];
                    vs += __shfl_xor_sync(0xffffffffu, vs, 1);
                    vs += __shfl_xor_sync(0xffffffffu, vs, 2);
                    vd += __shfl_xor_sync(0xffffffffu, vd, 1);
                    vd += __shfl_xor_sync(0xffffffffu, vd, 2);
                    if (t == 0) {
                        int r = gr0 + mt * 16 + g + rs * 8;
                        if (r < nrows) {
                            int head = ni * 2 + hh;
                            g_asrc[r * 4 + head] = vs;
                            g_adst[r * 4 + head] = vd;
                        }
                    }
                }
    } else {
        int cb = nbase - 128;
        #pragma unroll
        for (int mt = 0; mt < 2; mt++) {
            int r0 = gr0 + mt * 16 + g;
            int r1 = r0 + 8;
            #pragma unroll
            for (int nt = 0; nt < 8; nt++) {
                int col = cb + nt * 8 + t * 2;
                if (r0 < nrows)
                    *(float2*)(g_skip + (size_t)r0 * 128 + col) =
                        make_float2(acc[mt][nt][0], acc[mt][nt][1]);
                if (r1 < nrows)
                    *(float2*)(g_skip + (size_t)r1 * 128 + col) =
                        make_float2(acc[mt][nt][2], acc[mt][nt][3]);
            }
        }
    }
}

// ------------------- softmax aggregate: exact CSR, no-max exp, 4-edge batched --------
__global__ void __launch_bounds__(256)
agg_kernel(const float* __restrict__ bias, float* __restrict__ out, int N) {
    int gw = (blockIdx.x * blockDim.x + threadIdx.x) >> 5;
    int lane = threadIdx.x & 31;
    if (gw >= N) return;
    int n = gw;
    int beg = g_off[n];
    int end = g_off[n + 1];
    int head = lane >> 3;

    float adh = g_adst[n * 4 + head];
    const float4* h4 = (const float4*)g_h;

    float denom = 0.0f;
    float4 acc = make_float4(0.f, 0.f, 0.f, 0.f);

    int j = beg;
    for (; j + 4 <= end; j += 4) {
        int s0 = g_csr[j];
        int s1 = g_csr[j + 1];
        int s2 = g_csr[j + 2];
        int s3 = g_csr[j + 3];
        float a0 = g_asrc[s0 * 4 + head];
        float a1 = g_asrc[s1 * 4 + head];
        float a2 = g_asrc[s2 * 4 + head];
        float a3 = g_asrc[s3 * 4 + head];
        float4 v0 = h4[s0 * 32 + lane];
        float4 v1 = h4[s1 * 32 + lane];
        float4 v2 = h4[s2 * 32 + lane];
        float4 v3 = h4[s3 * 32 + lane];

        float e0 = a0 + adh; e0 = fmaxf(e0, NEG_SLOPE * e0);
        float e1 = a1 + adh; e1 = fmaxf(e1, NEG_SLOPE * e1);
        float e2 = a2 + adh; e2 = fmaxf(e2, NEG_SLOPE * e2);
        float e3 = a3 + adh; e3 = fmaxf(e3, NEG_SLOPE * e3);

        float w0 = __expf(e0);
        float w1 = __expf(e1);
        float w2 = __expf(e2);
        float w3 = __expf(e3);
        denom += (w0 + w1) + (w2 + w3);
        acc.x += w0 * v0.x + w1 * v1.x + w2 * v2.x + w3 * v3.x;
        acc.y += w0 * v0.y + w1 * v1.y + w2 * v2.y + w3 * v3.y;
        acc.z += w0 * v0.z + w1 * v1.z + w2 * v2.z + w3 * v3.z;
        acc.w += w0 * v0.w + w1 * v1.w + w2 * v2.w + w3 * v3.w;
    }
    for (; j < end; j++) {
        int s = g_csr[j];
        float a = g_asrc[s * 4 + head];
        float e = a + adh; e = fmaxf(e, NEG_SLOPE * e);
        float4 v = h4[s * 32 + lane];
        float w = __expf(e);
        denom += w;
        acc.x += w * v.x; acc.y += w * v.y; acc.z += w * v.z; acc.w += w * v.w;
    }

    float inv = 1.0f / (denom + 1e-16f);
    float4 b  = ((const float4*)bias)[lane];
    float4 sk = ((const float4*)g_skip)[(size_t)n * 32 + lane];
    float4 o;
    o.x = acc.x * inv + b.x + sk.x;
    o.y = acc.y * inv + b.y + sk.y;
    o.z = acc.z * inv + b.z + sk.z;
    o.w = acc.w * inv + b.w + sk.w;
    o.x = (o.x > 0.f) ? o.x : expm1f(o.x);
    o.y = (o.y > 0.f) ? o.y : expm1f(o.y);
    o.z = (o.z > 0.f) ? o.z : expm1f(o.z);
    o.w = (o.w > 0.f) ? o.w : expm1f(o.w);
    ((float4*)out)[(size_t)n * 32 + lane] = o;
}

// ------------------- launch -------------------
extern "C" void kernel_launch(void* const* d_in, const int* in_sizes, int n_in,
                              void* d_out, int out_size) {
    const float* x    = (const float*)d_in[0];
    const int*   ei   = (const int*)  d_in[1];
    const float* W1   = (const float*)d_in[2];
    const float* as1  = (const float*)d_in[3];
    const float* ad1  = (const float*)d_in[4];
    const float* b1   = (const float*)d_in[5];
    const float* Ws1  = (const float*)d_in[6];
    const float* W2   = (const float*)d_in[7];
    const float* as2  = (const float*)d_in[8];
    const float* ad2  = (const float*)d_in[9];
    const float* b2   = (const float*)d_in[10];
    const float* Ws2  = (const float*)d_in[11];

    int N = in_sizes[0] / DIM;
    int E = in_sizes[1] / 2;
    const int* src = ei;
    const int* dst = ei + E;

    float* buf1;  cudaGetSymbolAddress((void**)&buf1, g_buf1);
    __nv_bfloat16* bhi; cudaGetSymbolAddress((void**)&bhi, g_bhi);
    __nv_bfloat16* blo; cudaGetSymbolAddress((void**)&blo, g_blo);

    const size_t dyn = 27136 * 4;
    cudaFuncSetAttribute(gat_mma_fused, cudaFuncAttributeMaxDynamicSharedMemorySize, (int)dyn);

    int nb = (N + SCAN_CHUNK - 1) / SCAN_CHUNK;
    int gemm_blocks = (N + 63) / 64;
    int warp_blocks = (N * 32 + 255) / 256;

    // launch idx:
    prep_hist<<<WPREP_BLKS + 1024, 256>>>(W1, Ws1, W2, Ws2, dst, E);         // 0
    scan_lookback<<<nb, 256>>>(N);                                           // 1
    gat_mma_fused<<<gemm_blocks + SCAT_BLKS, 256, dyn>>>(                    // 2 (gemm1+scatter)
        x, (const uint32_t*)bhi, (const uint32_t*)blo, as1, ad1, N,
        gemm_blocks, src, dst, E);
    agg_kernel<<<warp_blocks, 256>>>(b1, buf1, N);                           // 3 <- profiled
    gat_mma_fused<<<gemm_blocks, 256, dyn>>>(                                // 4 (gemm2)
        buf1, (const uint32_t*)(bhi + 256 * 128), (const uint32_t*)(blo + 256 * 128),
        as2, ad2, N, gemm_blocks, nullptr, nullptr, 0);
    agg_kernel<<<warp_blocks, 256>>>(b2, (float*)d_out, N);                  // 5
}